// round 14
// baseline (speedup 1.0000x reference)
#include <cuda_runtime.h>
#include <cuda_bf16.h>
#include <cstdint>
#include <math.h>

#define Bz     32
#define Nn     100
#define Ff     514
#define FE     614      // 514 feats + 100 mask cols
#define ROWSE  101
#define NN2    10000
#define DIMMAX 10000
#define BLKP   128      // pairs per block in pair kernel
#define PBLK   79       // ceil(DIMMAX/128)
#define XPAD   36
#define ASTR   20       // word stride in ac GEMM smem (20 ≡ 4 mod 32 -> conflict-free)

// ---------------- scratch (static device globals; no allocation) ----------------
__device__ int   d_order[Bz * DIMMAX];
__device__ int   d_count[Bz];
__device__ float d_Gg[Bz * 64];
__device__ float d_A[Bz * Nn * 64];
__device__ float d_C[Bz * Nn * 64];
__device__ float d_logit[Bz * DIMMAX];   // holds e = exp(logit - shift)
__device__ float d_sig[Bz * DIMMAX];
__device__ float d_esum[Bz];
__device__ int   d_done[Bz];
__device__ uint4 d_Wpre4[2304];          // pair weights, split-bf16 padded layout

// ---------------- small helpers ----------------
__device__ __forceinline__ int read_dim(const int* p) {
    int v = *p;
    if (v < 1 || v > DIMMAX) {            // safety: tolerate float-encoded scalar
        float f = __int_as_float(v);
        v = (int)f;
    }
    if (v < 0) v = 0;
    if (v > DIMMAX) v = DIMMAX;
    return v;
}

// Eigen-style rational minimax tanh: 1 MUFU (rcp) instead of 2 (ex2+rcp).
__device__ __forceinline__ float my_tanh(float x) {
    x = fminf(fmaxf(x, -7.90531110763549805f), 7.90531110763549805f);
    float x2 = x * x;
    float p = fmaf(x2, -2.76076847742355e-16f, 2.00018790482477e-13f);
    p = fmaf(x2, p, -8.60467152213735e-11f);
    p = fmaf(x2, p, 5.12229709037114e-08f);
    p = fmaf(x2, p, 1.48572235717979e-05f);
    p = fmaf(x2, p, 6.37261928875436e-04f);
    p = fmaf(x2, p, 4.89352455891786e-03f);
    p = x * p;
    float q = fmaf(x2, 1.19825839466702e-06f, 1.18534705686654e-04f);
    q = fmaf(x2, q, 2.26843463243900e-03f);
    q = fmaf(x2, q, 4.89352518554385e-03f);
    return __fdividef(p, q);
}

__device__ __forceinline__ unsigned pack_bf(__nv_bfloat16 a, __nv_bfloat16 b) {
    __nv_bfloat162 v;
    v.x = a;  // low half
    v.y = b;  // high half
    return *reinterpret_cast<unsigned*>(&v);
}

__device__ __forceinline__ void split_word(float a, float b, unsigned& hw, unsigned& lw) {
    __nv_bfloat16 ha = __float2bfloat16(a), hb = __float2bfloat16(b);
    hw = pack_bf(ha, hb);
    lw = pack_bf(__float2bfloat16(a - __bfloat162float(ha)),
                 __float2bfloat16(b - __bfloat162float(hb)));
}

__device__ __forceinline__ void mma_bf16(float (&d)[4], const unsigned (&a)[4],
                                         const unsigned (&b)[2]) {
    asm volatile(
        "mma.sync.aligned.m16n8k16.row.col.f32.bf16.bf16.f32 "
        "{%0,%1,%2,%3}, {%4,%5,%6,%7}, {%8,%9}, {%0,%1,%2,%3};"
        : "+f"(d[0]), "+f"(d[1]), "+f"(d[2]), "+f"(d[3])
        : "r"(a[0]), "r"(a[1]), "r"(a[2]), "r"(a[3]), "r"(b[0]), "r"(b[1]));
}

// ================= prep kernel: flat 146 blocks: ac(50)/scan(32)/head(32)/zero(32)
// ac dynamic smem: 2 buffers x (128 W + 64 A rows) x 20 words x 2 (hi,lo) = 61440B
#define PREP_SMEM (2 * (128 + 64) * 2 * ASTR * 4)

__device__ void scan_role(const float* __restrict__ emb, int b, int dim, char* sh) {
    int t = threadIdx.x;           // 256
    int lane = t & 31, w = t >> 5; // 8 warps
    unsigned* bal = (unsigned*)sh;         // [320]
    int* pre = (int*)(sh + 320 * 4);       // [320]
    // phase 1: batched loads (20 in flight), then ballots
#pragma unroll
    for (int hf = 0; hf < 2; ++hf) {
        float v[20];
#pragma unroll
        for (int c2 = 0; c2 < 20; ++c2) {
            int c = hf * 20 + c2;
            int idx = c * 256 + t;
            float val = 0.f;
            if (idx < NN2) {
                int i = idx / Nn, j = idx - i * Nn;
                val = emb[(size_t)(b * ROWSE + 1 + i) * FE + Ff + j];
            }
            v[c2] = val;
        }
#pragma unroll
        for (int c2 = 0; c2 < 20; ++c2) {
            unsigned bl = __ballot_sync(0xffffffffu, v[c2] > 0.5f);
            if (lane == 0) bal[(hf * 20 + c2) * 8 + w] = bl;
        }
    }
    __syncthreads();
    if (t < 32) {
        int loc[10];
        int s = 0;
#pragma unroll
        for (int k = 0; k < 10; ++k) {
            int v = __popc(bal[lane * 10 + k]);
            loc[k] = s;
            s += v;
        }
        int p = s;
#pragma unroll
        for (int o = 1; o < 32; o <<= 1) {
            int n = __shfl_up_sync(0xffffffffu, p, o);
            if (lane >= o) p += n;
        }
        int off = p - s;
#pragma unroll
        for (int k = 0; k < 10; ++k) pre[lane * 10 + k] = off + loc[k];
        if (lane == 31) d_count[b] = p;
    }
    __syncthreads();
#pragma unroll
    for (int c = 0; c < 40; ++c) {
        unsigned bl = bal[c * 8 + w];
        if ((bl >> lane) & 1u) {
            int rank = pre[c * 8 + w] + __popc(bl & ((1u << lane) - 1u));
            if (rank < dim) d_order[b * DIMMAX + rank] = c * 256 + t;
        }
    }
}

__device__ void head_role(const float* __restrict__ emb,
                          const float* __restrict__ aw0, const float* __restrict__ ab0,
                          const float* __restrict__ cw0, const float* __restrict__ cb0,
                          const float* __restrict__ cw1, const float* __restrict__ cb1,
                          const float* __restrict__ cw2, const float* __restrict__ cb2,
                          const float* __restrict__ cw3, const float* __restrict__ cb3,
                          float* __restrict__ out, int voff, int b, char* sh) {
    float* row = (float*)sh;              // [516]
    float* part = row + 516;              // [256]
    float* ha = part + 256;               // [64]
    float* hb = ha + 64;                  // [64]
    int t = threadIdx.x;                  // 256
    for (int k = t; k < Ff; k += 256) row[k] = emb[(size_t)b * ROWSE * FE + k];
    __syncthreads();
    int j = t & 63, ks = t >> 6;  // 4-way k split
    {
        float acc = 0.f;
        for (int k = ks; k < Ff; k += 4) acc += row[k] * aw0[(size_t)k * 64 + j];
        part[t] = acc;
    }
    __syncthreads();
    if (t < 64) {
        float s = ab0[j] + part[j] + part[64 + j] + part[128 + j] + part[192 + j];
        d_Gg[b * 64 + j] = s;
    }
    __syncthreads();
    {
        float acc = 0.f;
        for (int k = ks; k < Ff; k += 4) acc += row[k] * cw0[(size_t)k * 64 + j];
        part[t] = acc;
    }
    __syncthreads();
    if (t < 64) {
        float s = cb0[j] + part[j] + part[64 + j] + part[128 + j] + part[192 + j];
        ha[j] = my_tanh(s);
    }
    __syncthreads();
    if (t < 64) {
        float acc = cb1[t];
        for (int k = 0; k < 64; ++k) acc += ha[k] * cw1[k * 64 + t];
        hb[t] = my_tanh(acc);
    }
    __syncthreads();
    if (t < 64) {
        float acc = cb2[t];
        for (int k = 0; k < 64; ++k) acc += hb[k] * cw2[k * 64 + t];
        ha[t] = my_tanh(acc);
    }
    __syncthreads();
    if (t == 0) {
        float v = cb3[0];
        for (int k = 0; k < 64; ++k) v += ha[k] * cw3[k];
        out[voff + b] = v;
    }
}

// [A|C] = nodes[3200,514] @ [W0_A | W0_C], bf16 3-term split tensor-core GEMM.
// 64-row x 128-col tiles (50 blocks), K padded 514 -> 544 (17 x k32 chunks).
__device__ void ac_mma_role(const float* __restrict__ emb,
                            const float* __restrict__ w0, int blk, char* sh) {
    int t = threadIdx.x;   // 256
    unsigned* buf = (unsigned*)sh;
    const int BUFW = (128 + 64) * 2 * ASTR;        // 7680 words per buffer
    const float* wA = w0 + (size_t)Ff * 64;        // A weights [514][64]
    const float* wC = wA + (size_t)Ff * 64;        // C weights [514][64]
    int m0 = blk * 64;

    // A staging: row = t>>2 (0..63), q = t&3 (4 threads/row, 4 words each)
    int arow = t >> 2, q = t & 3;
    int gr = m0 + arow;
    int bb = gr / Nn, node = gr - bb * Nn;
    const float* asrc = emb + (size_t)(bb * ROWSE + 1 + node) * FE;

    float wreg[16];
    float areg[8];

#define ACL(kb)                                                              \
    do {                                                                     \
        _Pragma("unroll") for (int i = 0; i < 8; ++i) {                      \
            int e = t + 256 * i;                                             \
            int n = e & 127, wd = e >> 7;                                    \
            int k0 = (kb) + 2 * wd;                                          \
            const float* src = (n < 64) ? (wA + n) : (wC + (n - 64));        \
            wreg[2 * i] = (k0 < Ff) ? src[(size_t)k0 * 64] : 0.f;            \
            wreg[2 * i + 1] = (k0 + 1 < Ff) ? src[(size_t)(k0 + 1) * 64] : 0.f; \
        }                                                                    \
        _Pragma("unroll") for (int jj = 0; jj < 4; ++jj) {                   \
            int ka = (kb) + 8 * q + 2 * jj;                                  \
            float2 v2 = make_float2(0.f, 0.f);                               \
            if (ka < Ff) {                                                   \
                v2 = *(const float2*)(asrc + ka);                            \
                if (ka + 1 >= Ff) v2.y = 0.f;                                \
            }                                                                \
            areg[2 * jj] = v2.x;                                             \
            areg[2 * jj + 1] = v2.y;                                         \
        }                                                                    \
    } while (0)

#define ACS(dst)                                                             \
    do {                                                                     \
        unsigned* Wh_ = (dst);                                               \
        unsigned* Wl_ = Wh_ + 128 * ASTR;                                    \
        unsigned* Ah_ = Wl_ + 128 * ASTR;                                    \
        unsigned* Al_ = Ah_ + 64 * ASTR;                                     \
        _Pragma("unroll") for (int i = 0; i < 8; ++i) {                      \
            int e = t + 256 * i;                                             \
            int n = e & 127, wd = e >> 7;                                    \
            unsigned hw, lw;                                                 \
            split_word(wreg[2 * i], wreg[2 * i + 1], hw, lw);                \
            Wh_[n * ASTR + wd] = hw;                                         \
            Wl_[n * ASTR + wd] = lw;                                         \
        }                                                                    \
        _Pragma("unroll") for (int jj = 0; jj < 4; ++jj) {                   \
            unsigned hw, lw;                                                 \
            split_word(areg[2 * jj], areg[2 * jj + 1], hw, lw);              \
            Ah_[arow * ASTR + q * 4 + jj] = hw;                              \
            Al_[arow * ASTR + q * 4 + jj] = lw;                              \
        }                                                                    \
    } while (0)

    ACL(0);
    ACS(buf);
    ACL(32);   // regs now hold chunk 1
    __syncthreads();

    int w = t >> 5, lane = t & 31;
    int r = lane >> 2, c = lane & 3;
    int ms = (w & 3) * 16;       // m-strip base within 64-row tile
    int ng = (w >> 2) * 64;      // n-group base (8 n8 tiles)

    float acc[8][4];
#pragma unroll
    for (int nt = 0; nt < 8; ++nt)
#pragma unroll
        for (int i2 = 0; i2 < 4; ++i2) acc[nt][i2] = 0.f;

    for (int kc = 0; kc < 17; ++kc) {
        unsigned* cur = buf + (kc & 1) * BUFW;
        unsigned* alt = buf + ((kc & 1) ^ 1) * BUFW;
        const unsigned* Wh = cur;
        const unsigned* Wl = Wh + 128 * ASTR;
        const unsigned* Ah = Wl + 128 * ASTR;
        const unsigned* Al = Ah + 64 * ASTR;
#pragma unroll
        for (int s2 = 0; s2 < 2; ++s2) {
            int kwb = s2 * 8;
            const unsigned* aha = Ah + (ms + r) * ASTR + kwb;
            const unsigned* ala = Al + (ms + r) * ASTR + kwb;
            unsigned ah[4] = {aha[c], aha[8 * ASTR + c], aha[c + 4], aha[8 * ASTR + c + 4]};
            unsigned al[4] = {ala[c], ala[8 * ASTR + c], ala[c + 4], ala[8 * ASTR + c + 4]};
#pragma unroll
            for (int nt = 0; nt < 8; ++nt) {
                const unsigned* wh = Wh + (ng + nt * 8 + r) * ASTR + kwb;
                const unsigned* wl = Wl + (ng + nt * 8 + r) * ASTR + kwb;
                unsigned bh[2] = {wh[c], wh[c + 4]};
                unsigned bl[2] = {wl[c], wl[c + 4]};
                mma_bf16(acc[nt], ah, bh);   // a_hi * w_hi
                mma_bf16(acc[nt], al, bh);   // a_lo * w_hi
                mma_bf16(acc[nt], ah, bl);   // a_hi * w_lo
            }
        }
        if (kc < 16) {
            ACS(alt);                            // store chunk kc+1
            if (kc < 15) ACL((kc + 2) * 32);     // load chunk kc+2
        }
        __syncthreads();
    }
#undef ACL
#undef ACS

    // epilogue: fp32 results -> d_A / d_C
#pragma unroll
    for (int nt = 0; nt < 8; ++nt) {
        int j = ng + nt * 8 + 2 * c;
        int gr0 = m0 + ms + r, gr1 = gr0 + 8;
        float* dst = (j < 64) ? d_A : d_C;
        int jj = (j < 64) ? j : j - 64;
        *(float2*)(dst + (size_t)gr0 * 64 + jj) = make_float2(acc[nt][0], acc[nt][1]);
        *(float2*)(dst + (size_t)gr1 * 64 + jj) = make_float2(acc[nt][2], acc[nt][3]);
    }
}

// zero output slab + esum + done, and convert this block's slice of pair weights
__device__ void zero_role(float* __restrict__ out, int b,
                          const float* __restrict__ aw1,
                          const float* __restrict__ aw2) {
    float4 z = make_float4(0.f, 0.f, 0.f, 0.f);
    float4* ob = (float4*)(out + (size_t)b * 20000);
    int t = threadIdx.x;
    for (int i = t; i < 5000; i += 256) ob[i] = z;
    if (t == 0) d_esum[b] = 0.f;
    if (t == 1) d_done[b] = 0;
    // convert slice: elements e in [b*128, b*128+128) of aw1 and aw2
    if (t < 128) {
        __nv_bfloat16* wp = (__nv_bfloat16*)d_Wpre4;
        int e = b * 128 + t;
        int k = e >> 6, n = e & 63;
        int ei = n * 72 + k;
        float w1v = aw1[e], w2v = aw2[e];
        __nv_bfloat16 h1 = __float2bfloat16(w1v);
        wp[0 * 4608 + ei] = h1;
        wp[1 * 4608 + ei] = __float2bfloat16(w1v - __bfloat162float(h1));
        __nv_bfloat16 h2 = __float2bfloat16(w2v);
        wp[2 * 4608 + ei] = h2;
        wp[3 * 4608 + ei] = __float2bfloat16(w2v - __bfloat162float(h2));
    }
}

__global__ void prep_kernel(const float* __restrict__ emb,
                            const float* __restrict__ aw0, const float* __restrict__ ab0,
                            const float* __restrict__ aw1, const float* __restrict__ aw2,
                            const float* __restrict__ cw0, const float* __restrict__ cb0,
                            const float* __restrict__ cw1, const float* __restrict__ cb1,
                            const float* __restrict__ cw2, const float* __restrict__ cb2,
                            const float* __restrict__ cw3, const float* __restrict__ cb3,
                            float* __restrict__ out, int voff,
                            const int* __restrict__ dimp) {
    extern __shared__ __align__(16) char sh[];
    int bid = blockIdx.x;
    if (bid < 50) {
        ac_mma_role(emb, aw0, bid, sh);
    } else if (bid < 82) {
        scan_role(emb, bid - 50, read_dim(dimp), sh);
    } else if (bid < 114) {
        head_role(emb, aw0, ab0, cw0, cb0, cw1, cb1, cw2, cb2, cw3, cb3,
                  out, voff, bid - 82, sh);
    } else {
        zero_role(out, bid - 114, aw1, aw2);
    }
}

// ============== pair kernel v9b: bf16 MMA + fused last-block scatter ============
// 128 pairs/block, 8 warps; warp owns a 16-row m-strip through both layers.
// X, W stored as bf16x2 words (hi + lo arrays), XPAD=36 => conflict-free frags.
// FINAL layer stores fp32 IN-PLACE per row: cols 0..31 -> Xh row, cols 32..63 ->
// Xl row (each warp touches only its own rows => __syncwarp suffices, no race).
struct PairSmem {
    unsigned Wh1[64 * XPAD], Wl1[64 * XPAD];
    unsigned Wh2[64 * XPAD], Wl2[64 * XPAD];
    unsigned Xh[128 * XPAD], Xl[128 * XPAD];
    float W3[128];                // [k][2]
    float b1[64], b2[64], b0[64], Gg[64];
    float b3[2];
    float epart[8];
    int   lastflag;
};
#define PAIR_SMEM_BYTES ((int)sizeof(PairSmem))

template <bool FINAL>
__device__ __forceinline__ void mma_layer(unsigned* __restrict__ Xh,
                                          unsigned* __restrict__ Xl,
                                          const unsigned* __restrict__ Wh,
                                          const unsigned* __restrict__ Wl,
                                          const float* __restrict__ bias,
                                          int w, int lane) {
    int r = lane >> 2, c = lane & 3;
    float acc[8][4];
#pragma unroll
    for (int nt = 0; nt < 8; ++nt) {
        float bv0 = bias[nt * 8 + 2 * c], bv1 = bias[nt * 8 + 2 * c + 1];
        acc[nt][0] = bv0; acc[nt][1] = bv1; acc[nt][2] = bv0; acc[nt][3] = bv1;
    }
    const unsigned* XhA = Xh + (w * 16 + r) * XPAD;
    const unsigned* XhB = XhA + 8 * XPAD;
    const unsigned* XlA = Xl + (w * 16 + r) * XPAD;
    const unsigned* XlB = XlA + 8 * XPAD;
#pragma unroll
    for (int s = 0; s < 4; ++s) {
        unsigned ah[4] = {XhA[s * 8 + c], XhB[s * 8 + c],
                          XhA[s * 8 + c + 4], XhB[s * 8 + c + 4]};
        unsigned al[4] = {XlA[s * 8 + c], XlB[s * 8 + c],
                          XlA[s * 8 + c + 4], XlB[s * 8 + c + 4]};
#pragma unroll
        for (int nt = 0; nt < 8; ++nt) {
            const unsigned* wh = Wh + (nt * 8 + r) * XPAD + s * 8;
            const unsigned* wl = Wl + (nt * 8 + r) * XPAD + s * 8;
            unsigned bh[2] = {wh[c], wh[c + 4]};
            unsigned bl[2] = {wl[c], wl[c + 4]};
            mma_bf16(acc[nt], ah, bh);   // x_hi * w_hi
            mma_bf16(acc[nt], al, bh);   // x_lo * w_hi
            mma_bf16(acc[nt], ah, bl);   // x_hi * w_lo
        }
    }
    __syncwarp();   // own-strip rows only; warp-local handoff
    if (FINAL) {
        // fp32 in-place: cols 0..31 -> Xh rows, cols 32..63 -> Xl rows
        float* XhF = (float*)Xh;
        float* XlF = (float*)Xl;
        int row0 = w * 16 + r, row1 = row0 + 8;
#pragma unroll
        for (int nt = 0; nt < 8; ++nt) {
            int col = nt * 8 + 2 * c;
            float* base0, *base1;
            int cc;
            if (col < 32) {
                base0 = XhF + row0 * XPAD;
                base1 = XhF + row1 * XPAD;
                cc = col;
            } else {
                base0 = XlF + row0 * XPAD;
                base1 = XlF + row1 * XPAD;
                cc = col - 32;
            }
            *(float2*)(base0 + cc) = make_float2(my_tanh(acc[nt][0]), my_tanh(acc[nt][1]));
            *(float2*)(base1 + cc) = make_float2(my_tanh(acc[nt][2]), my_tanh(acc[nt][3]));
        }
    } else {
        unsigned* XhO = Xh + (w * 16 + r) * XPAD;
        unsigned* XhO8 = XhO + 8 * XPAD;
        unsigned* XlO = Xl + (w * 16 + r) * XPAD;
        unsigned* XlO8 = XlO + 8 * XPAD;
#pragma unroll
        for (int nt = 0; nt < 8; ++nt) {
            int kw = nt * 4 + c;
            float t0 = my_tanh(acc[nt][0]), t1 = my_tanh(acc[nt][1]);
            float t2 = my_tanh(acc[nt][2]), t3 = my_tanh(acc[nt][3]);
            unsigned hw, lw;
            split_word(t0, t1, hw, lw);
            XhO[kw] = hw;
            XlO[kw] = lw;
            split_word(t2, t3, hw, lw);
            XhO8[kw] = hw;
            XlO8[kw] = lw;
        }
    }
    __syncwarp();
}

__global__ __launch_bounds__(256, 2) void pair_kernel(
    const float* __restrict__ ab1, const float* __restrict__ ab2,
    const float* __restrict__ aw3, const float* __restrict__ ab3,
    const float* __restrict__ ab0, const int* __restrict__ dimp,
    float* __restrict__ out) {
    extern __shared__ __align__(16) char smem_raw[];
    PairSmem* sm = (PairSmem*)smem_raw;
    int dim = read_dim(dimp);
    int p0 = blockIdx.x * BLKP;
    if (p0 >= dim) return;               // uniform block exit
    int b = blockIdx.y, t = threadIdx.x;

    // ---- copy preconverted split-bf16 weights (4 contiguous arrays) ----
    {
        uint4* dstv = (uint4*)sm->Wh1;
#pragma unroll
        for (int i = 0; i < 9; ++i) dstv[t + 256 * i] = d_Wpre4[t + 256 * i];
        if (t < 64) {
            sm->b1[t] = ab1[t];
            sm->b2[t] = ab2[t];
            sm->b0[t] = ab0[t];
            sm->Gg[t] = d_Gg[b * 64 + t];
            sm->W3[2 * t + 0] = aw3[2 * t + 0];
            sm->W3[2 * t + 1] = aw3[2 * t + 1];
        }
        if (t < 2) sm->b3[t] = ab3[t];
    }
    __syncthreads();

    // shift SA = sum_k |W3[k][0]|  (logit part <= SA since |h| < 1)
    float SA = 0.f;
#pragma unroll
    for (int k = 0; k < 64; ++k) SA += fabsf(sm->W3[2 * k]);

    // ---- layer 0: 2 threads per pair, each builds 32 features as hi/lo words ----
    {
        int lp = t >> 1, half = t & 1;
        int p = p0 + lp;
        int cnt = d_count[b];
        int kb = half * 32;
        unsigned* xh = sm->Xh + lp * XPAD + half * 16;
        unsigned* xl = sm->Xl + lp * XPAD + half * 16;
        float v[32];
        if (p < cnt && p < dim) {
            int q = d_order[b * DIMMAX + p];
            int i1 = q / Nn, i2 = q - i1 * Nn;
            const float4* Ga = (const float4*)(d_A + ((size_t)(b * Nn + i1)) * 64 + kb);
            const float4* Cc = (const float4*)(d_C + ((size_t)(b * Nn + i2)) * 64 + kb);
#pragma unroll
            for (int kk = 0; kk < 8; ++kk) {
                float4 a = Ga[kk], c4 = Cc[kk];
                int k = kb + 4 * kk;
                v[4 * kk + 0] = my_tanh(sm->Gg[k + 0] + a.x + c4.x);
                v[4 * kk + 1] = my_tanh(sm->Gg[k + 1] + a.y + c4.y);
                v[4 * kk + 2] = my_tanh(sm->Gg[k + 2] + a.z + c4.z);
                v[4 * kk + 3] = my_tanh(sm->Gg[k + 3] + a.w + c4.w);
            }
        } else {
            // invalid / out-of-range: zeroed input -> pre-activation = b0
#pragma unroll
            for (int kk = 0; kk < 32; ++kk) v[kk] = my_tanh(sm->b0[kb + kk]);
        }
#pragma unroll
        for (int kk2 = 0; kk2 < 16; ++kk2) {
            unsigned hw, lw;
            split_word(v[2 * kk2], v[2 * kk2 + 1], hw, lw);
            xh[kk2] = hw;
            xl[kk2] = lw;
        }
    }
    __syncwarp();

    int w = t >> 5, lane = t & 31;
    mma_layer<false>(sm->Xh, sm->Xl, sm->Wh1, sm->Wl1, sm->b1, w, lane);
    mma_layer<true>(sm->Xh, sm->Xl, sm->Wh2, sm->Wl2, sm->b2, w, lane);

    // ---- layer 3 + block partial softmax sum ----
    float ev = 0.f;
    {
        int lp = t >> 1, half = t & 1;
        int p = p0 + lp;
        // fp32 final activations: cols 0..31 in Xh rows, 32..63 in Xl rows
        const float* xr = (half == 0 ? (const float*)sm->Xh : (const float*)sm->Xl)
                          + lp * XPAD;
        float lg = 0.f, bq = 0.f;
        int kb = half * 32;
#pragma unroll
        for (int kk = 0; kk < 32; ++kk) {
            float h = xr[kk];
            lg += h * sm->W3[2 * (kb + kk) + 0];
            bq += h * sm->W3[2 * (kb + kk) + 1];
        }
        lg += __shfl_xor_sync(0xffffffffu, lg, 1);
        bq += __shfl_xor_sync(0xffffffffu, bq, 1);
        if (half == 0 && p < dim) {
            // e = exp(logit - (b3 + SA)); softmax is shift-invariant
            float e = __expf(lg - SA);
            d_logit[b * DIMMAX + p] = e;
            d_sig[b * DIMMAX + p] = 1.0f / (1.0f + __expf(-(bq + sm->b3[1])));
            ev = e;
        }
    }
    // block-level sum of e -> atomic into d_esum[b]
#pragma unroll
    for (int o = 16; o; o >>= 1) ev += __shfl_xor_sync(0xffffffffu, ev, o);
    if (lane == 0) sm->epart[w] = ev;
    __syncthreads();
    if (t == 0) {
        float s2 = 0.f;
#pragma unroll
        for (int i = 0; i < 8; ++i) s2 += sm->epart[i];
        atomicAdd(&d_esum[b], s2);
        __threadfence();
        int nblk = (dim + BLKP - 1) / BLKP;
        if (nblk > PBLK) nblk = PBLK;
        int old = atomicAdd(&d_done[b], 1);
        sm->lastflag = (old == nblk - 1);
    }
    __syncthreads();
    // ---- last block for this batch: normalize + scatter the whole batch ----
    if (sm->lastflag) {
        __threadfence();
        float inv = 1.0f / d_esum[b];
        int cnt = d_count[b];
        int lim = (cnt < dim) ? cnt : dim;
        float* ob = out + (size_t)b * 20000;
        for (int p = t; p < lim; p += 256) {
            int q = d_order[b * DIMMAX + p];
            float pi = d_logit[b * DIMMAX + p] * inv;
            float sg = d_sig[b * DIMMAX + p];
            ob[q] = pi * sg;
            ob[10000 + q] = pi * (1.0f - sg);
        }
    }
}

// ---------------- launcher (2 launches, single stream) ----------------
extern "C" void kernel_launch(void* const* d_in, const int* in_sizes, int n_in,
                              void* d_out, int out_size) {
    const float* emb = (const float*)d_in[0];
    const int* dimp;
    int base;
    if (n_in >= 18 && in_sizes[1] == 1) {   // dict order: emb, dim, actor..., critic...
        dimp = (const int*)d_in[1];
        base = 2;
    } else {                                // signature order: emb, actor..., critic..., dim
        dimp = (const int*)d_in[n_in - 1];
        base = 1;
    }
    const float* aw0 = (const float*)d_in[base + 0];
    const float* ab0 = (const float*)d_in[base + 1];
    const float* aw1 = (const float*)d_in[base + 2];
    const float* ab1 = (const float*)d_in[base + 3];
    const float* aw2 = (const float*)d_in[base + 4];
    const float* ab2 = (const float*)d_in[base + 5];
    const float* aw3 = (const float*)d_in[base + 6];
    const float* ab3 = (const float*)d_in[base + 7];
    const float* cw0 = (const float*)d_in[base + 8];
    const float* cb0 = (const float*)d_in[base + 9];
    const float* cw1 = (const float*)d_in[base + 10];
    const float* cb1 = (const float*)d_in[base + 11];
    const float* cw2 = (const float*)d_in[base + 12];
    const float* cb2 = (const float*)d_in[base + 13];
    const float* cw3 = (const float*)d_in[base + 14];
    const float* cb3 = (const float*)d_in[base + 15];

    float* out = (float*)d_out;
    int voff = out_size - Bz;  // value slot after the filled region (expect 640000)

    static int init_done = 0;
    if (!init_done) {
        cudaFuncSetAttribute(pair_kernel, cudaFuncAttributeMaxDynamicSharedMemorySize,
                             PAIR_SMEM_BYTES);
        cudaFuncSetAttribute(prep_kernel, cudaFuncAttributeMaxDynamicSharedMemorySize,
                             PREP_SMEM);
        init_done = 1;
    }

    prep_kernel<<<146, 256, PREP_SMEM>>>(emb, aw0, ab0, aw1, aw2,
                                         cw0, cb0, cw1, cb1, cw2, cb2,
                                         cw3, cb3, out, voff, dimp);
    pair_kernel<<<dim3(PBLK, Bz), 256, PAIR_SMEM_BYTES>>>(ab1, ab2, aw3, ab3,
                                                          ab0, dimp, out);
}

// round 15
// speedup vs baseline: 1.0840x; 1.0840x over previous
#include <cuda_runtime.h>
#include <cuda_bf16.h>
#include <cstdint>
#include <math.h>

#define Bz     32
#define Nn     100
#define Ff     514
#define FE     614      // 514 feats + 100 mask cols
#define ROWSE  101
#define NN2    10000
#define DIMMAX 10000
#define BLKP   128      // pairs per block in pair kernel
#define PBLK   79       // ceil(DIMMAX/128)
#define XPAD   36
#define ASTR   20       // word stride in ac GEMM smem (20 ≡ 4 mod 32 -> conflict-free)

// ---------------- scratch (static device globals; no allocation) ----------------
__device__ int   d_order[Bz * DIMMAX];
__device__ int   d_count[Bz];
__device__ float d_Gg[Bz * 64];
__device__ float d_A[Bz * Nn * 64];
__device__ float d_C[Bz * Nn * 64];
__device__ float d_logit[Bz * DIMMAX];   // holds e = exp(logit - shift)
__device__ float d_sig[Bz * DIMMAX];
__device__ float d_esum[Bz];
__device__ uint4 d_Wpre4[2304];          // pair weights, split-bf16 padded layout

// ---------------- small helpers ----------------
__device__ __forceinline__ int read_dim(const int* p) {
    int v = *p;
    if (v < 1 || v > DIMMAX) {            // safety: tolerate float-encoded scalar
        float f = __int_as_float(v);
        v = (int)f;
    }
    if (v < 0) v = 0;
    if (v > DIMMAX) v = DIMMAX;
    return v;
}

// Eigen-style rational minimax tanh: 1 MUFU (rcp) instead of 2 (ex2+rcp).
__device__ __forceinline__ float my_tanh(float x) {
    x = fminf(fmaxf(x, -7.90531110763549805f), 7.90531110763549805f);
    float x2 = x * x;
    float p = fmaf(x2, -2.76076847742355e-16f, 2.00018790482477e-13f);
    p = fmaf(x2, p, -8.60467152213735e-11f);
    p = fmaf(x2, p, 5.12229709037114e-08f);
    p = fmaf(x2, p, 1.48572235717979e-05f);
    p = fmaf(x2, p, 6.37261928875436e-04f);
    p = fmaf(x2, p, 4.89352455891786e-03f);
    p = x * p;
    float q = fmaf(x2, 1.19825839466702e-06f, 1.18534705686654e-04f);
    q = fmaf(x2, q, 2.26843463243900e-03f);
    q = fmaf(x2, q, 4.89352518554385e-03f);
    return __fdividef(p, q);
}

__device__ __forceinline__ unsigned pack_bf(__nv_bfloat16 a, __nv_bfloat16 b) {
    __nv_bfloat162 v;
    v.x = a;  // low half
    v.y = b;  // high half
    return *reinterpret_cast<unsigned*>(&v);
}

__device__ __forceinline__ void split_word(float a, float b, unsigned& hw, unsigned& lw) {
    __nv_bfloat16 ha = __float2bfloat16(a), hb = __float2bfloat16(b);
    hw = pack_bf(ha, hb);
    lw = pack_bf(__float2bfloat16(a - __bfloat162float(ha)),
                 __float2bfloat16(b - __bfloat162float(hb)));
}

__device__ __forceinline__ void mma_bf16(float (&d)[4], const unsigned (&a)[4],
                                         const unsigned (&b)[2]) {
    asm volatile(
        "mma.sync.aligned.m16n8k16.row.col.f32.bf16.bf16.f32 "
        "{%0,%1,%2,%3}, {%4,%5,%6,%7}, {%8,%9}, {%0,%1,%2,%3};"
        : "+f"(d[0]), "+f"(d[1]), "+f"(d[2]), "+f"(d[3])
        : "r"(a[0]), "r"(a[1]), "r"(a[2]), "r"(a[3]), "r"(b[0]), "r"(b[1]));
}

// ================= prep kernel: flat 146 blocks: ac(50)/scan(32)/head(32)/zero(32)
// ac dynamic smem: 2 buffers x (128 W + 64 A rows) x 20 words x 2 (hi,lo) = 61440B
#define PREP_SMEM (2 * (128 + 64) * 2 * ASTR * 4)

__device__ void scan_role(const float* __restrict__ emb, int b, int dim, char* sh) {
    int t = threadIdx.x;           // 256
    int lane = t & 31, w = t >> 5; // 8 warps
    unsigned* bal = (unsigned*)sh;         // [320]
    int* pre = (int*)(sh + 320 * 4);       // [320]
    // phase 1: batched loads (20 in flight), then ballots
#pragma unroll
    for (int hf = 0; hf < 2; ++hf) {
        float v[20];
#pragma unroll
        for (int c2 = 0; c2 < 20; ++c2) {
            int c = hf * 20 + c2;
            int idx = c * 256 + t;
            float val = 0.f;
            if (idx < NN2) {
                int i = idx / Nn, j = idx - i * Nn;
                val = emb[(size_t)(b * ROWSE + 1 + i) * FE + Ff + j];
            }
            v[c2] = val;
        }
#pragma unroll
        for (int c2 = 0; c2 < 20; ++c2) {
            unsigned bl = __ballot_sync(0xffffffffu, v[c2] > 0.5f);
            if (lane == 0) bal[(hf * 20 + c2) * 8 + w] = bl;
        }
    }
    __syncthreads();
    if (t < 32) {
        int loc[10];
        int s = 0;
#pragma unroll
        for (int k = 0; k < 10; ++k) {
            int v = __popc(bal[lane * 10 + k]);
            loc[k] = s;
            s += v;
        }
        int p = s;
#pragma unroll
        for (int o = 1; o < 32; o <<= 1) {
            int n = __shfl_up_sync(0xffffffffu, p, o);
            if (lane >= o) p += n;
        }
        int off = p - s;
#pragma unroll
        for (int k = 0; k < 10; ++k) pre[lane * 10 + k] = off + loc[k];
        if (lane == 31) d_count[b] = p;
    }
    __syncthreads();
#pragma unroll
    for (int c = 0; c < 40; ++c) {
        unsigned bl = bal[c * 8 + w];
        if ((bl >> lane) & 1u) {
            int rank = pre[c * 8 + w] + __popc(bl & ((1u << lane) - 1u));
            if (rank < dim) d_order[b * DIMMAX + rank] = c * 256 + t;
        }
    }
}

__device__ void head_role(const float* __restrict__ emb,
                          const float* __restrict__ aw0, const float* __restrict__ ab0,
                          const float* __restrict__ cw0, const float* __restrict__ cb0,
                          const float* __restrict__ cw1, const float* __restrict__ cb1,
                          const float* __restrict__ cw2, const float* __restrict__ cb2,
                          const float* __restrict__ cw3, const float* __restrict__ cb3,
                          float* __restrict__ out, int voff, int b, char* sh) {
    float* row = (float*)sh;              // [516]
    float* part = row + 516;              // [256]
    float* ha = part + 256;               // [64]
    float* hb = ha + 64;                  // [64]
    int t = threadIdx.x;                  // 256
    for (int k = t; k < Ff; k += 256) row[k] = emb[(size_t)b * ROWSE * FE + k];
    __syncthreads();
    int j = t & 63, ks = t >> 6;  // 4-way k split
    {
        float acc = 0.f;
        for (int k = ks; k < Ff; k += 4) acc += row[k] * aw0[(size_t)k * 64 + j];
        part[t] = acc;
    }
    __syncthreads();
    if (t < 64) {
        float s = ab0[j] + part[j] + part[64 + j] + part[128 + j] + part[192 + j];
        d_Gg[b * 64 + j] = s;
    }
    __syncthreads();
    {
        float acc = 0.f;
        for (int k = ks; k < Ff; k += 4) acc += row[k] * cw0[(size_t)k * 64 + j];
        part[t] = acc;
    }
    __syncthreads();
    if (t < 64) {
        float s = cb0[j] + part[j] + part[64 + j] + part[128 + j] + part[192 + j];
        ha[j] = my_tanh(s);
    }
    __syncthreads();
    if (t < 64) {
        float acc = cb1[t];
        for (int k = 0; k < 64; ++k) acc += ha[k] * cw1[k * 64 + t];
        hb[t] = my_tanh(acc);
    }
    __syncthreads();
    if (t < 64) {
        float acc = cb2[t];
        for (int k = 0; k < 64; ++k) acc += hb[k] * cw2[k * 64 + t];
        ha[t] = my_tanh(acc);
    }
    __syncthreads();
    if (t == 0) {
        float v = cb3[0];
        for (int k = 0; k < 64; ++k) v += ha[k] * cw3[k];
        out[voff + b] = v;
    }
}

// [A|C] = nodes[3200,514] @ [W0_A | W0_C], bf16 3-term split tensor-core GEMM.
// 64-row x 128-col tiles (50 blocks), K padded 514 -> 544 (17 x k32 chunks).
__device__ void ac_mma_role(const float* __restrict__ emb,
                            const float* __restrict__ w0, int blk, char* sh) {
    int t = threadIdx.x;   // 256
    unsigned* buf = (unsigned*)sh;
    const int BUFW = (128 + 64) * 2 * ASTR;        // 7680 words per buffer
    const float* wA = w0 + (size_t)Ff * 64;        // A weights [514][64]
    const float* wC = wA + (size_t)Ff * 64;        // C weights [514][64]
    int m0 = blk * 64;

    // A staging: row = t>>2 (0..63), q = t&3 (4 threads/row, 4 words each)
    int arow = t >> 2, q = t & 3;
    int gr = m0 + arow;
    int bb = gr / Nn, node = gr - bb * Nn;
    const float* asrc = emb + (size_t)(bb * ROWSE + 1 + node) * FE;

    float wreg[16];
    float areg[8];

#define ACL(kb)                                                              \
    do {                                                                     \
        _Pragma("unroll") for (int i = 0; i < 8; ++i) {                      \
            int e = t + 256 * i;                                             \
            int n = e & 127, wd = e >> 7;                                    \
            int k0 = (kb) + 2 * wd;                                          \
            const float* src = (n < 64) ? (wA + n) : (wC + (n - 64));        \
            wreg[2 * i] = (k0 < Ff) ? src[(size_t)k0 * 64] : 0.f;            \
            wreg[2 * i + 1] = (k0 + 1 < Ff) ? src[(size_t)(k0 + 1) * 64] : 0.f; \
        }                                                                    \
        _Pragma("unroll") for (int jj = 0; jj < 4; ++jj) {                   \
            int ka = (kb) + 8 * q + 2 * jj;                                  \
            float2 v2 = make_float2(0.f, 0.f);                               \
            if (ka < Ff) {                                                   \
                v2 = *(const float2*)(asrc + ka);                            \
                if (ka + 1 >= Ff) v2.y = 0.f;                                \
            }                                                                \
            areg[2 * jj] = v2.x;                                             \
            areg[2 * jj + 1] = v2.y;                                         \
        }                                                                    \
    } while (0)

#define ACS(dst)                                                             \
    do {                                                                     \
        unsigned* Wh_ = (dst);                                               \
        unsigned* Wl_ = Wh_ + 128 * ASTR;                                    \
        unsigned* Ah_ = Wl_ + 128 * ASTR;                                    \
        unsigned* Al_ = Ah_ + 64 * ASTR;                                     \
        _Pragma("unroll") for (int i = 0; i < 8; ++i) {                      \
            int e = t + 256 * i;                                             \
            int n = e & 127, wd = e >> 7;                                    \
            unsigned hw, lw;                                                 \
            split_word(wreg[2 * i], wreg[2 * i + 1], hw, lw);                \
            Wh_[n * ASTR + wd] = hw;                                         \
            Wl_[n * ASTR + wd] = lw;                                         \
        }                                                                    \
        _Pragma("unroll") for (int jj = 0; jj < 4; ++jj) {                   \
            unsigned hw, lw;                                                 \
            split_word(areg[2 * jj], areg[2 * jj + 1], hw, lw);              \
            Ah_[arow * ASTR + q * 4 + jj] = hw;                              \
            Al_[arow * ASTR + q * 4 + jj] = lw;                              \
        }                                                                    \
    } while (0)

    ACL(0);
    ACS(buf);
    ACL(32);   // regs now hold chunk 1
    __syncthreads();

    int w = t >> 5, lane = t & 31;
    int r = lane >> 2, c = lane & 3;
    int ms = (w & 3) * 16;       // m-strip base within 64-row tile
    int ng = (w >> 2) * 64;      // n-group base (8 n8 tiles)

    float acc[8][4];
#pragma unroll
    for (int nt = 0; nt < 8; ++nt)
#pragma unroll
        for (int i2 = 0; i2 < 4; ++i2) acc[nt][i2] = 0.f;

    for (int kc = 0; kc < 17; ++kc) {
        unsigned* cur = buf + (kc & 1) * BUFW;
        unsigned* alt = buf + ((kc & 1) ^ 1) * BUFW;
        const unsigned* Wh = cur;
        const unsigned* Wl = Wh + 128 * ASTR;
        const unsigned* Ah = Wl + 128 * ASTR;
        const unsigned* Al = Ah + 64 * ASTR;
#pragma unroll
        for (int s2 = 0; s2 < 2; ++s2) {
            int kwb = s2 * 8;
            const unsigned* aha = Ah + (ms + r) * ASTR + kwb;
            const unsigned* ala = Al + (ms + r) * ASTR + kwb;
            unsigned ah[4] = {aha[c], aha[8 * ASTR + c], aha[c + 4], aha[8 * ASTR + c + 4]};
            unsigned al[4] = {ala[c], ala[8 * ASTR + c], ala[c + 4], ala[8 * ASTR + c + 4]};
#pragma unroll
            for (int nt = 0; nt < 8; ++nt) {
                const unsigned* wh = Wh + (ng + nt * 8 + r) * ASTR + kwb;
                const unsigned* wl = Wl + (ng + nt * 8 + r) * ASTR + kwb;
                unsigned bh[2] = {wh[c], wh[c + 4]};
                unsigned bl[2] = {wl[c], wl[c + 4]};
                mma_bf16(acc[nt], ah, bh);   // a_hi * w_hi
                mma_bf16(acc[nt], al, bh);   // a_lo * w_hi
                mma_bf16(acc[nt], ah, bl);   // a_hi * w_lo
            }
        }
        if (kc < 16) {
            ACS(alt);                            // store chunk kc+1
            if (kc < 15) ACL((kc + 2) * 32);     // load chunk kc+2
        }
        __syncthreads();
    }
#undef ACL
#undef ACS

    // epilogue: fp32 results -> d_A / d_C
#pragma unroll
    for (int nt = 0; nt < 8; ++nt) {
        int j = ng + nt * 8 + 2 * c;
        int gr0 = m0 + ms + r, gr1 = gr0 + 8;
        float* dst = (j < 64) ? d_A : d_C;
        int jj = (j < 64) ? j : j - 64;
        *(float2*)(dst + (size_t)gr0 * 64 + jj) = make_float2(acc[nt][0], acc[nt][1]);
        *(float2*)(dst + (size_t)gr1 * 64 + jj) = make_float2(acc[nt][2], acc[nt][3]);
    }
}

// zero output slab + esum, and convert this block's slice of pair weights
__device__ void zero_role(float* __restrict__ out, int b,
                          const float* __restrict__ aw1,
                          const float* __restrict__ aw2) {
    float4 z = make_float4(0.f, 0.f, 0.f, 0.f);
    float4* ob = (float4*)(out + (size_t)b * 20000);
    int t = threadIdx.x;
    for (int i = t; i < 5000; i += 256) ob[i] = z;
    if (t == 0) d_esum[b] = 0.f;
    // convert slice: elements e in [b*128, b*128+128) of aw1 and aw2
    if (t < 128) {
        __nv_bfloat16* wp = (__nv_bfloat16*)d_Wpre4;
        int e = b * 128 + t;
        int k = e >> 6, n = e & 63;
        int ei = n * 72 + k;
        float w1v = aw1[e], w2v = aw2[e];
        __nv_bfloat16 h1 = __float2bfloat16(w1v);
        wp[0 * 4608 + ei] = h1;
        wp[1 * 4608 + ei] = __float2bfloat16(w1v - __bfloat162float(h1));
        __nv_bfloat16 h2 = __float2bfloat16(w2v);
        wp[2 * 4608 + ei] = h2;
        wp[3 * 4608 + ei] = __float2bfloat16(w2v - __bfloat162float(h2));
    }
}

__global__ void prep_kernel(const float* __restrict__ emb,
                            const float* __restrict__ aw0, const float* __restrict__ ab0,
                            const float* __restrict__ aw1, const float* __restrict__ aw2,
                            const float* __restrict__ cw0, const float* __restrict__ cb0,
                            const float* __restrict__ cw1, const float* __restrict__ cb1,
                            const float* __restrict__ cw2, const float* __restrict__ cb2,
                            const float* __restrict__ cw3, const float* __restrict__ cb3,
                            float* __restrict__ out, int voff,
                            const int* __restrict__ dimp) {
    extern __shared__ __align__(16) char sh[];
    int bid = blockIdx.x;
    if (bid < 50) {
        ac_mma_role(emb, aw0, bid, sh);
    } else if (bid < 82) {
        scan_role(emb, bid - 50, read_dim(dimp), sh);
    } else if (bid < 114) {
        head_role(emb, aw0, ab0, cw0, cb0, cw1, cb1, cw2, cb2, cw3, cb3,
                  out, voff, bid - 82, sh);
    } else {
        zero_role(out, bid - 114, aw1, aw2);
    }
}

// ============== pair kernel v8: bf16 m16n8k16 MMA, preconverted weights =========
// 128 pairs/block, 8 warps; warp owns a 16-row m-strip through both layers.
// X, W stored as bf16x2 words (hi + lo arrays), XPAD=36 => conflict-free frags.
struct PairSmem {
    unsigned Wh1[64 * XPAD], Wl1[64 * XPAD];
    unsigned Wh2[64 * XPAD], Wl2[64 * XPAD];
    unsigned Xh[128 * XPAD], Xl[128 * XPAD];
    float W3[128];                // [k][2]
    float b1[64], b2[64], b0[64], Gg[64];
    float b3[2];
    float epart[8];
};
#define PAIR_SMEM_BYTES ((int)sizeof(PairSmem))

__device__ __forceinline__ void mma_layer(unsigned* __restrict__ Xh,
                                          unsigned* __restrict__ Xl,
                                          const unsigned* __restrict__ Wh,
                                          const unsigned* __restrict__ Wl,
                                          const float* __restrict__ bias,
                                          int w, int lane) {
    int r = lane >> 2, c = lane & 3;
    float acc[8][4];
#pragma unroll
    for (int nt = 0; nt < 8; ++nt) {
        float bv0 = bias[nt * 8 + 2 * c], bv1 = bias[nt * 8 + 2 * c + 1];
        acc[nt][0] = bv0; acc[nt][1] = bv1; acc[nt][2] = bv0; acc[nt][3] = bv1;
    }
    const unsigned* XhA = Xh + (w * 16 + r) * XPAD;
    const unsigned* XhB = XhA + 8 * XPAD;
    const unsigned* XlA = Xl + (w * 16 + r) * XPAD;
    const unsigned* XlB = XlA + 8 * XPAD;
#pragma unroll
    for (int s = 0; s < 4; ++s) {
        unsigned ah[4] = {XhA[s * 8 + c], XhB[s * 8 + c],
                          XhA[s * 8 + c + 4], XhB[s * 8 + c + 4]};
        unsigned al[4] = {XlA[s * 8 + c], XlB[s * 8 + c],
                          XlA[s * 8 + c + 4], XlB[s * 8 + c + 4]};
#pragma unroll
        for (int nt = 0; nt < 8; ++nt) {
            const unsigned* wh = Wh + (nt * 8 + r) * XPAD + s * 8;
            const unsigned* wl = Wl + (nt * 8 + r) * XPAD + s * 8;
            unsigned bh[2] = {wh[c], wh[c + 4]};
            unsigned bl[2] = {wl[c], wl[c + 4]};
            mma_bf16(acc[nt], ah, bh);   // x_hi * w_hi
            mma_bf16(acc[nt], al, bh);   // x_lo * w_hi
            mma_bf16(acc[nt], ah, bl);   // x_hi * w_lo
        }
    }
    __syncwarp();   // own-strip rows only; warp-local handoff
    unsigned* XhO = Xh + (w * 16 + r) * XPAD;
    unsigned* XhO8 = XhO + 8 * XPAD;
    unsigned* XlO = Xl + (w * 16 + r) * XPAD;
    unsigned* XlO8 = XlO + 8 * XPAD;
#pragma unroll
    for (int nt = 0; nt < 8; ++nt) {
        int kw = nt * 4 + c;
        float t0 = my_tanh(acc[nt][0]), t1 = my_tanh(acc[nt][1]);
        float t2 = my_tanh(acc[nt][2]), t3 = my_tanh(acc[nt][3]);
        unsigned hw, lw;
        split_word(t0, t1, hw, lw);
        XhO[kw] = hw;
        XlO[kw] = lw;
        split_word(t2, t3, hw, lw);
        XhO8[kw] = hw;
        XlO8[kw] = lw;
    }
    __syncwarp();
}

__global__ __launch_bounds__(256, 2) void pair_kernel(
    const float* __restrict__ ab1, const float* __restrict__ ab2,
    const float* __restrict__ aw3, const float* __restrict__ ab3,
    const float* __restrict__ ab0, const int* __restrict__ dimp) {
    extern __shared__ __align__(16) char smem_raw[];
    PairSmem* sm = (PairSmem*)smem_raw;
    int dim = read_dim(dimp);
    int p0 = blockIdx.x * BLKP;
    if (p0 >= dim) return;               // uniform block exit
    int b = blockIdx.y, t = threadIdx.x;

    // ---- copy preconverted split-bf16 weights (4 contiguous arrays) ----
    {
        uint4* dstv = (uint4*)sm->Wh1;
#pragma unroll
        for (int i = 0; i < 9; ++i) dstv[t + 256 * i] = d_Wpre4[t + 256 * i];
        if (t < 64) {
            sm->b1[t] = ab1[t];
            sm->b2[t] = ab2[t];
            sm->b0[t] = ab0[t];
            sm->Gg[t] = d_Gg[b * 64 + t];
            sm->W3[2 * t + 0] = aw3[2 * t + 0];
            sm->W3[2 * t + 1] = aw3[2 * t + 1];
        }
        if (t < 2) sm->b3[t] = ab3[t];
    }
    __syncthreads();

    // shift SA = sum_k |W3[k][0]|  (logit part <= SA since |h| < 1)
    float SA = 0.f;
#pragma unroll
    for (int k = 0; k < 64; ++k) SA += fabsf(sm->W3[2 * k]);

    // ---- layer 0: 2 threads per pair, each builds 32 features as hi/lo words ----
    {
        int lp = t >> 1, half = t & 1;
        int p = p0 + lp;
        int cnt = d_count[b];
        int kb = half * 32;
        unsigned* xh = sm->Xh + lp * XPAD + half * 16;
        unsigned* xl = sm->Xl + lp * XPAD + half * 16;
        float v[32];
        if (p < cnt && p < dim) {
            int q = d_order[b * DIMMAX + p];
            int i1 = q / Nn, i2 = q - i1 * Nn;
            const float4* Ga = (const float4*)(d_A + ((size_t)(b * Nn + i1)) * 64 + kb);
            const float4* Cc = (const float4*)(d_C + ((size_t)(b * Nn + i2)) * 64 + kb);
#pragma unroll
            for (int kk = 0; kk < 8; ++kk) {
                float4 a = Ga[kk], c4 = Cc[kk];
                int k = kb + 4 * kk;
                v[4 * kk + 0] = my_tanh(sm->Gg[k + 0] + a.x + c4.x);
                v[4 * kk + 1] = my_tanh(sm->Gg[k + 1] + a.y + c4.y);
                v[4 * kk + 2] = my_tanh(sm->Gg[k + 2] + a.z + c4.z);
                v[4 * kk + 3] = my_tanh(sm->Gg[k + 3] + a.w + c4.w);
            }
        } else {
            // invalid / out-of-range: zeroed input -> pre-activation = b0
#pragma unroll
            for (int kk = 0; kk < 32; ++kk) v[kk] = my_tanh(sm->b0[kb + kk]);
        }
#pragma unroll
        for (int kk2 = 0; kk2 < 16; ++kk2) {
            unsigned hw, lw;
            split_word(v[2 * kk2], v[2 * kk2 + 1], hw, lw);
            xh[kk2] = hw;
            xl[kk2] = lw;
        }
    }
    __syncwarp();

    int w = t >> 5, lane = t & 31;
    mma_layer(sm->Xh, sm->Xl, sm->Wh1, sm->Wl1, sm->b1, w, lane);
    mma_layer(sm->Xh, sm->Xl, sm->Wh2, sm->Wl2, sm->b2, w, lane);

    // ---- layer 3 + block partial softmax sum ----
    float ev = 0.f;
    {
        int lp = t >> 1, half = t & 1;
        int p = p0 + lp;
        const unsigned* xh = sm->Xh + lp * XPAD + half * 16;
        const unsigned* xl = sm->Xl + lp * XPAD + half * 16;
        float lg = 0.f, bq = 0.f;
        int kb = half * 32;
#pragma unroll
        for (int kk2 = 0; kk2 < 16; ++kk2) {
            __nv_bfloat162 hh = *reinterpret_cast<const __nv_bfloat162*>(xh + kk2);
            __nv_bfloat162 ll = *reinterpret_cast<const __nv_bfloat162*>(xl + kk2);
            float h0 = __bfloat162float(hh.x) + __bfloat162float(ll.x);
            float h1 = __bfloat162float(hh.y) + __bfloat162float(ll.y);
            int k = kb + 2 * kk2;
            lg += h0 * sm->W3[2 * k + 0] + h1 * sm->W3[2 * k + 2];
            bq += h0 * sm->W3[2 * k + 1] + h1 * sm->W3[2 * k + 3];
        }
        lg += __shfl_xor_sync(0xffffffffu, lg, 1);
        bq += __shfl_xor_sync(0xffffffffu, bq, 1);
        if (half == 0 && p < dim) {
            // e = exp(logit - (b3 + SA)); softmax is shift-invariant
            float e = __expf(lg - SA);
            d_logit[b * DIMMAX + p] = e;
            d_sig[b * DIMMAX + p] = 1.0f / (1.0f + __expf(-(bq + sm->b3[1])));
            ev = e;
        }
    }
    // block-level sum of e -> atomic into d_esum[b]
#pragma unroll
    for (int o = 16; o; o >>= 1) ev += __shfl_xor_sync(0xffffffffu, ev, o);
    if (lane == 0) sm->epart[w] = ev;
    __syncthreads();
    if (t == 0) {
        float s2 = 0.f;
#pragma unroll
        for (int i = 0; i < 8; ++i) s2 += sm->epart[i];
        atomicAdd(&d_esum[b], s2);
    }
}

// ---------------- kernel 3: wide normalize + scatter ----------------
__global__ void scatter_kernel(float* __restrict__ out, const int* __restrict__ dimp) {
    int dim = read_dim(dimp);
    int b = blockIdx.y;
    int p = blockIdx.x * 256 + threadIdx.x;
    if (p >= dim) return;
    if (p >= d_count[b]) return;  // valid == 0 -> contributes zeros only
    float inv = 1.0f / d_esum[b];
    int q = d_order[b * DIMMAX + p];
    float pi = d_logit[b * DIMMAX + p] * inv;
    float sg = d_sig[b * DIMMAX + p];
    float* ob = out + (size_t)b * 20000;
    ob[q] = pi * sg;
    ob[10000 + q] = pi * (1.0f - sg);
}

// ---------------- launcher (3 launches, single stream) ----------------
extern "C" void kernel_launch(void* const* d_in, const int* in_sizes, int n_in,
                              void* d_out, int out_size) {
    const float* emb = (const float*)d_in[0];
    const int* dimp;
    int base;
    if (n_in >= 18 && in_sizes[1] == 1) {   // dict order: emb, dim, actor..., critic...
        dimp = (const int*)d_in[1];
        base = 2;
    } else {                                // signature order: emb, actor..., critic..., dim
        dimp = (const int*)d_in[n_in - 1];
        base = 1;
    }
    const float* aw0 = (const float*)d_in[base + 0];
    const float* ab0 = (const float*)d_in[base + 1];
    const float* aw1 = (const float*)d_in[base + 2];
    const float* ab1 = (const float*)d_in[base + 3];
    const float* aw2 = (const float*)d_in[base + 4];
    const float* ab2 = (const float*)d_in[base + 5];
    const float* aw3 = (const float*)d_in[base + 6];
    const float* ab3 = (const float*)d_in[base + 7];
    const float* cw0 = (const float*)d_in[base + 8];
    const float* cb0 = (const float*)d_in[base + 9];
    const float* cw1 = (const float*)d_in[base + 10];
    const float* cb1 = (const float*)d_in[base + 11];
    const float* cw2 = (const float*)d_in[base + 12];
    const float* cb2 = (const float*)d_in[base + 13];
    const float* cw3 = (const float*)d_in[base + 14];
    const float* cb3 = (const float*)d_in[base + 15];

    float* out = (float*)d_out;
    int voff = out_size - Bz;  // value slot after the filled region (expect 640000)

    static int init_done = 0;
    if (!init_done) {
        cudaFuncSetAttribute(pair_kernel, cudaFuncAttributeMaxDynamicSharedMemorySize,
                             PAIR_SMEM_BYTES);
        cudaFuncSetAttribute(prep_kernel, cudaFuncAttributeMaxDynamicSharedMemorySize,
                             PREP_SMEM);
        init_done = 1;
    }

    prep_kernel<<<146, 256, PREP_SMEM>>>(emb, aw0, ab0, aw1, aw2,
                                         cw0, cb0, cw1, cb1, cw2, cb2,
                                         cw3, cb3, out, voff, dimp);
    pair_kernel<<<dim3(PBLK, Bz), 256, PAIR_SMEM_BYTES>>>(ab1, ab2, aw3, ab3,
                                                          ab0, dimp);
    scatter_kernel<<<dim3(40, Bz), 256>>>(out, dimp);
}

// round 16
// speedup vs baseline: 1.1327x; 1.0449x over previous
#include <cuda_runtime.h>
#include <cuda_bf16.h>
#include <cstdint>
#include <math.h>

#define Bz     32
#define Nn     100
#define Ff     514
#define FE     614      // 514 feats + 100 mask cols
#define ROWSE  101
#define NN2    10000
#define DIMMAX 10000
#define BLKP   128      // pairs per block in pair kernel
#define PBLK   79       // ceil(DIMMAX/128)
#define XPAD   36
#define ASTR   20       // word stride in ac GEMM smem (20 ≡ 4 mod 32 -> conflict-free)

// ---------------- scratch (static device globals; no allocation) ----------------
__device__ int   d_order[Bz * DIMMAX];
__device__ int   d_count[Bz];
__device__ float d_Gg[Bz * 64];
__device__ float d_A[Bz * Nn * 64];
__device__ float d_C[Bz * Nn * 64];
__device__ float d_logit[Bz * DIMMAX];   // holds e = exp(logit - shift)
__device__ float d_sig[Bz * DIMMAX];
__device__ float d_esum[Bz];
__device__ uint4 d_Wpre4[2304];          // pair weights, split-bf16 padded layout

// ---------------- small helpers ----------------
__device__ __forceinline__ int read_dim(const int* p) {
    int v = *p;
    if (v < 1 || v > DIMMAX) {            // safety: tolerate float-encoded scalar
        float f = __int_as_float(v);
        v = (int)f;
    }
    if (v < 0) v = 0;
    if (v > DIMMAX) v = DIMMAX;
    return v;
}

// Eigen-style rational minimax tanh: 1 MUFU (rcp) instead of 2 (ex2+rcp).
__device__ __forceinline__ float my_tanh(float x) {
    x = fminf(fmaxf(x, -7.90531110763549805f), 7.90531110763549805f);
    float x2 = x * x;
    float p = fmaf(x2, -2.76076847742355e-16f, 2.00018790482477e-13f);
    p = fmaf(x2, p, -8.60467152213735e-11f);
    p = fmaf(x2, p, 5.12229709037114e-08f);
    p = fmaf(x2, p, 1.48572235717979e-05f);
    p = fmaf(x2, p, 6.37261928875436e-04f);
    p = fmaf(x2, p, 4.89352455891786e-03f);
    p = x * p;
    float q = fmaf(x2, 1.19825839466702e-06f, 1.18534705686654e-04f);
    q = fmaf(x2, q, 2.26843463243900e-03f);
    q = fmaf(x2, q, 4.89352518554385e-03f);
    return __fdividef(p, q);
}

__device__ __forceinline__ unsigned pack_bf(__nv_bfloat16 a, __nv_bfloat16 b) {
    __nv_bfloat162 v;
    v.x = a;  // low half
    v.y = b;  // high half
    return *reinterpret_cast<unsigned*>(&v);
}

__device__ __forceinline__ void split_word(float a, float b, unsigned& hw, unsigned& lw) {
    __nv_bfloat16 ha = __float2bfloat16(a), hb = __float2bfloat16(b);
    hw = pack_bf(ha, hb);
    lw = pack_bf(__float2bfloat16(a - __bfloat162float(ha)),
                 __float2bfloat16(b - __bfloat162float(hb)));
}

__device__ __forceinline__ void mma_bf16(float (&d)[4], const unsigned (&a)[4],
                                         const unsigned (&b)[2]) {
    asm volatile(
        "mma.sync.aligned.m16n8k16.row.col.f32.bf16.bf16.f32 "
        "{%0,%1,%2,%3}, {%4,%5,%6,%7}, {%8,%9}, {%0,%1,%2,%3};"
        : "+f"(d[0]), "+f"(d[1]), "+f"(d[2]), "+f"(d[3])
        : "r"(a[0]), "r"(a[1]), "r"(a[2]), "r"(a[3]), "r"(b[0]), "r"(b[1]));
}

// ================= prep kernel: flat 146 blocks: ac(50)/scan(32)/head(32)/zero(32)
// ac dynamic smem: 2 buffers x (128 W + 64 A rows) x 20 words x 2 (hi,lo) = 61440B
#define PREP_SMEM (2 * (128 + 64) * 2 * ASTR * 4)

__device__ void scan_role(const float* __restrict__ emb, int b, int dim, char* sh) {
    int t = threadIdx.x;           // 256
    int lane = t & 31, w = t >> 5; // 8 warps
    unsigned* bal = (unsigned*)sh;         // [320]
    int* pre = (int*)(sh + 320 * 4);       // [320]
    // phase 1: batched loads (20 in flight), then ballots
#pragma unroll
    for (int hf = 0; hf < 2; ++hf) {
        float v[20];
#pragma unroll
        for (int c2 = 0; c2 < 20; ++c2) {
            int c = hf * 20 + c2;
            int idx = c * 256 + t;
            float val = 0.f;
            if (idx < NN2) {
                int i = idx / Nn, j = idx - i * Nn;
                val = emb[(size_t)(b * ROWSE + 1 + i) * FE + Ff + j];
            }
            v[c2] = val;
        }
#pragma unroll
        for (int c2 = 0; c2 < 20; ++c2) {
            unsigned bl = __ballot_sync(0xffffffffu, v[c2] > 0.5f);
            if (lane == 0) bal[(hf * 20 + c2) * 8 + w] = bl;
        }
    }
    __syncthreads();
    if (t < 32) {
        int loc[10];
        int s = 0;
#pragma unroll
        for (int k = 0; k < 10; ++k) {
            int v = __popc(bal[lane * 10 + k]);
            loc[k] = s;
            s += v;
        }
        int p = s;
#pragma unroll
        for (int o = 1; o < 32; o <<= 1) {
            int n = __shfl_up_sync(0xffffffffu, p, o);
            if (lane >= o) p += n;
        }
        int off = p - s;
#pragma unroll
        for (int k = 0; k < 10; ++k) pre[lane * 10 + k] = off + loc[k];
        if (lane == 31) d_count[b] = p;
    }
    __syncthreads();
#pragma unroll
    for (int c = 0; c < 40; ++c) {
        unsigned bl = bal[c * 8 + w];
        if ((bl >> lane) & 1u) {
            int rank = pre[c * 8 + w] + __popc(bl & ((1u << lane) - 1u));
            if (rank < dim) d_order[b * DIMMAX + rank] = c * 256 + t;
        }
    }
}

__device__ void head_role(const float* __restrict__ emb,
                          const float* __restrict__ aw0, const float* __restrict__ ab0,
                          const float* __restrict__ cw0, const float* __restrict__ cb0,
                          const float* __restrict__ cw1, const float* __restrict__ cb1,
                          const float* __restrict__ cw2, const float* __restrict__ cb2,
                          const float* __restrict__ cw3, const float* __restrict__ cb3,
                          float* __restrict__ out, int voff, int b, char* sh) {
    float* row = (float*)sh;              // [516]
    float* part = row + 516;              // [256]
    float* ha = part + 256;               // [64]
    float* hb = ha + 64;                  // [64]
    int t = threadIdx.x;                  // 256
    for (int k = t; k < Ff; k += 256) row[k] = emb[(size_t)b * ROWSE * FE + k];
    __syncthreads();
    int j = t & 63, ks = t >> 6;  // 4-way k split
    {
        float acc = 0.f;
        for (int k = ks; k < Ff; k += 4) acc += row[k] * aw0[(size_t)k * 64 + j];
        part[t] = acc;
    }
    __syncthreads();
    if (t < 64) {
        float s = ab0[j] + part[j] + part[64 + j] + part[128 + j] + part[192 + j];
        d_Gg[b * 64 + j] = s;
    }
    __syncthreads();
    {
        float acc = 0.f;
        for (int k = ks; k < Ff; k += 4) acc += row[k] * cw0[(size_t)k * 64 + j];
        part[t] = acc;
    }
    __syncthreads();
    if (t < 64) {
        float s = cb0[j] + part[j] + part[64 + j] + part[128 + j] + part[192 + j];
        ha[j] = my_tanh(s);
    }
    __syncthreads();
    if (t < 64) {
        float acc = cb1[t];
        for (int k = 0; k < 64; ++k) acc += ha[k] * cw1[k * 64 + t];
        hb[t] = my_tanh(acc);
    }
    __syncthreads();
    if (t < 64) {
        float acc = cb2[t];
        for (int k = 0; k < 64; ++k) acc += hb[k] * cw2[k * 64 + t];
        ha[t] = my_tanh(acc);
    }
    __syncthreads();
    if (t == 0) {
        float v = cb3[0];
        for (int k = 0; k < 64; ++k) v += ha[k] * cw3[k];
        out[voff + b] = v;
    }
}

// [A|C] = nodes[3200,514] @ [W0_A | W0_C], bf16 3-term split tensor-core GEMM.
// 64-row x 128-col tiles (50 blocks), K padded 514 -> 544 (17 x k32 chunks).
__device__ void ac_mma_role(const float* __restrict__ emb,
                            const float* __restrict__ w0, int blk, char* sh) {
    int t = threadIdx.x;   // 256
    unsigned* buf = (unsigned*)sh;
    const int BUFW = (128 + 64) * 2 * ASTR;        // 7680 words per buffer
    const float* wA = w0 + (size_t)Ff * 64;        // A weights [514][64]
    const float* wC = wA + (size_t)Ff * 64;        // C weights [514][64]
    int m0 = blk * 64;

    // A staging: row = t>>2 (0..63), q = t&3 (4 threads/row, 4 words each)
    int arow = t >> 2, q = t & 3;
    int gr = m0 + arow;
    int bb = gr / Nn, node = gr - bb * Nn;
    const float* asrc = emb + (size_t)(bb * ROWSE + 1 + node) * FE;

    float wreg[16];
    float areg[8];

#define ACL(kb)                                                              \
    do {                                                                     \
        _Pragma("unroll") for (int i = 0; i < 8; ++i) {                      \
            int e = t + 256 * i;                                             \
            int n = e & 127, wd = e >> 7;                                    \
            int k0 = (kb) + 2 * wd;                                          \
            const float* src = (n < 64) ? (wA + n) : (wC + (n - 64));        \
            wreg[2 * i] = (k0 < Ff) ? src[(size_t)k0 * 64] : 0.f;            \
            wreg[2 * i + 1] = (k0 + 1 < Ff) ? src[(size_t)(k0 + 1) * 64] : 0.f; \
        }                                                                    \
        _Pragma("unroll") for (int jj = 0; jj < 4; ++jj) {                   \
            int ka = (kb) + 8 * q + 2 * jj;                                  \
            float2 v2 = make_float2(0.f, 0.f);                               \
            if (ka < Ff) {                                                   \
                v2 = *(const float2*)(asrc + ka);                            \
                if (ka + 1 >= Ff) v2.y = 0.f;                                \
            }                                                                \
            areg[2 * jj] = v2.x;                                             \
            areg[2 * jj + 1] = v2.y;                                         \
        }                                                                    \
    } while (0)

#define ACS(dst)                                                             \
    do {                                                                     \
        unsigned* Wh_ = (dst);                                               \
        unsigned* Wl_ = Wh_ + 128 * ASTR;                                    \
        unsigned* Ah_ = Wl_ + 128 * ASTR;                                    \
        unsigned* Al_ = Ah_ + 64 * ASTR;                                     \
        _Pragma("unroll") for (int i = 0; i < 8; ++i) {                      \
            int e = t + 256 * i;                                             \
            int n = e & 127, wd = e >> 7;                                    \
            unsigned hw, lw;                                                 \
            split_word(wreg[2 * i], wreg[2 * i + 1], hw, lw);                \
            Wh_[n * ASTR + wd] = hw;                                         \
            Wl_[n * ASTR + wd] = lw;                                         \
        }                                                                    \
        _Pragma("unroll") for (int jj = 0; jj < 4; ++jj) {                   \
            unsigned hw, lw;                                                 \
            split_word(areg[2 * jj], areg[2 * jj + 1], hw, lw);              \
            Ah_[arow * ASTR + q * 4 + jj] = hw;                              \
            Al_[arow * ASTR + q * 4 + jj] = lw;                              \
        }                                                                    \
    } while (0)

    ACL(0);
    ACS(buf);
    ACL(32);   // regs now hold chunk 1
    __syncthreads();

    int w = t >> 5, lane = t & 31;
    int r = lane >> 2, c = lane & 3;
    int ms = (w & 3) * 16;       // m-strip base within 64-row tile
    int ng = (w >> 2) * 64;      // n-group base (8 n8 tiles)

    float acc[8][4];
#pragma unroll
    for (int nt = 0; nt < 8; ++nt)
#pragma unroll
        for (int i2 = 0; i2 < 4; ++i2) acc[nt][i2] = 0.f;

    for (int kc = 0; kc < 17; ++kc) {
        unsigned* cur = buf + (kc & 1) * BUFW;
        unsigned* alt = buf + ((kc & 1) ^ 1) * BUFW;
        const unsigned* Wh = cur;
        const unsigned* Wl = Wh + 128 * ASTR;
        const unsigned* Ah = Wl + 128 * ASTR;
        const unsigned* Al = Ah + 64 * ASTR;
#pragma unroll
        for (int s2 = 0; s2 < 2; ++s2) {
            int kwb = s2 * 8;
            const unsigned* aha = Ah + (ms + r) * ASTR + kwb;
            const unsigned* ala = Al + (ms + r) * ASTR + kwb;
            unsigned ah[4] = {aha[c], aha[8 * ASTR + c], aha[c + 4], aha[8 * ASTR + c + 4]};
            unsigned al[4] = {ala[c], ala[8 * ASTR + c], ala[c + 4], ala[8 * ASTR + c + 4]};
#pragma unroll
            for (int nt = 0; nt < 8; ++nt) {
                const unsigned* wh = Wh + (ng + nt * 8 + r) * ASTR + kwb;
                const unsigned* wl = Wl + (ng + nt * 8 + r) * ASTR + kwb;
                unsigned bh[2] = {wh[c], wh[c + 4]};
                unsigned bl[2] = {wl[c], wl[c + 4]};
                mma_bf16(acc[nt], ah, bh);   // a_hi * w_hi
                mma_bf16(acc[nt], al, bh);   // a_lo * w_hi
                mma_bf16(acc[nt], ah, bl);   // a_hi * w_lo
            }
        }
        if (kc < 16) {
            ACS(alt);                            // store chunk kc+1
            if (kc < 15) ACL((kc + 2) * 32);     // load chunk kc+2
        }
        __syncthreads();
    }
#undef ACL
#undef ACS

    // epilogue: fp32 results -> d_A / d_C
#pragma unroll
    for (int nt = 0; nt < 8; ++nt) {
        int j = ng + nt * 8 + 2 * c;
        int gr0 = m0 + ms + r, gr1 = gr0 + 8;
        float* dst = (j < 64) ? d_A : d_C;
        int jj = (j < 64) ? j : j - 64;
        *(float2*)(dst + (size_t)gr0 * 64 + jj) = make_float2(acc[nt][0], acc[nt][1]);
        *(float2*)(dst + (size_t)gr1 * 64 + jj) = make_float2(acc[nt][2], acc[nt][3]);
    }
}

// zero output slab + esum, and convert this block's slice of pair weights
__device__ void zero_role(float* __restrict__ out, int b,
                          const float* __restrict__ aw1,
                          const float* __restrict__ aw2) {
    float4 z = make_float4(0.f, 0.f, 0.f, 0.f);
    float4* ob = (float4*)(out + (size_t)b * 20000);
    int t = threadIdx.x;
    for (int i = t; i < 5000; i += 256) ob[i] = z;
    if (t == 0) d_esum[b] = 0.f;
    // convert slice: elements e in [b*128, b*128+128) of aw1 and aw2
    if (t < 128) {
        __nv_bfloat16* wp = (__nv_bfloat16*)d_Wpre4;
        int e = b * 128 + t;
        int k = e >> 6, n = e & 63;
        int ei = n * 72 + k;
        float w1v = aw1[e], w2v = aw2[e];
        __nv_bfloat16 h1 = __float2bfloat16(w1v);
        wp[0 * 4608 + ei] = h1;
        wp[1 * 4608 + ei] = __float2bfloat16(w1v - __bfloat162float(h1));
        __nv_bfloat16 h2 = __float2bfloat16(w2v);
        wp[2 * 4608 + ei] = h2;
        wp[3 * 4608 + ei] = __float2bfloat16(w2v - __bfloat162float(h2));
    }
}

__global__ void prep_kernel(const float* __restrict__ emb,
                            const float* __restrict__ aw0, const float* __restrict__ ab0,
                            const float* __restrict__ aw1, const float* __restrict__ aw2,
                            const float* __restrict__ cw0, const float* __restrict__ cb0,
                            const float* __restrict__ cw1, const float* __restrict__ cb1,
                            const float* __restrict__ cw2, const float* __restrict__ cb2,
                            const float* __restrict__ cw3, const float* __restrict__ cb3,
                            float* __restrict__ out, int voff,
                            const int* __restrict__ dimp) {
    extern __shared__ __align__(16) char sh[];
    int bid = blockIdx.x;
    if (bid < 50) {
        ac_mma_role(emb, aw0, bid, sh);
    } else if (bid < 82) {
        scan_role(emb, bid - 50, read_dim(dimp), sh);
    } else if (bid < 114) {
        head_role(emb, aw0, ab0, cw0, cb0, cw1, cb1, cw2, cb2, cw3, cb3,
                  out, voff, bid - 82, sh);
    } else {
        zero_role(out, bid - 114, aw1, aw2);
    }
}

// ============== pair kernel v8b: bf16 m16n8k16 MMA, preconverted weights ========
// 128 pairs/block, 8 warps; warp owns a 16-row m-strip through both layers.
// X, W stored as bf16x2 words (hi + lo arrays), XPAD=36 => conflict-free frags.
struct PairSmem {
    unsigned Wh1[64 * XPAD], Wl1[64 * XPAD];
    unsigned Wh2[64 * XPAD], Wl2[64 * XPAD];
    unsigned Xh[128 * XPAD], Xl[128 * XPAD];
    float W3[128];                // [k][2]
    float b1[64], b2[64], b0[64], Gg[64];
    float b3[2];
    float epart[8];
    float sSA;
};
#define PAIR_SMEM_BYTES ((int)sizeof(PairSmem))

__device__ __forceinline__ void mma_layer(unsigned* __restrict__ Xh,
                                          unsigned* __restrict__ Xl,
                                          const unsigned* __restrict__ Wh,
                                          const unsigned* __restrict__ Wl,
                                          const float* __restrict__ bias,
                                          int w, int lane) {
    int r = lane >> 2, c = lane & 3;
    float acc[8][4];
#pragma unroll
    for (int nt = 0; nt < 8; ++nt) {
        float bv0 = bias[nt * 8 + 2 * c], bv1 = bias[nt * 8 + 2 * c + 1];
        acc[nt][0] = bv0; acc[nt][1] = bv1; acc[nt][2] = bv0; acc[nt][3] = bv1;
    }
    const unsigned* XhA = Xh + (w * 16 + r) * XPAD;
    const unsigned* XhB = XhA + 8 * XPAD;
    const unsigned* XlA = Xl + (w * 16 + r) * XPAD;
    const unsigned* XlB = XlA + 8 * XPAD;
#pragma unroll
    for (int s = 0; s < 4; ++s) {
        unsigned ah[4] = {XhA[s * 8 + c], XhB[s * 8 + c],
                          XhA[s * 8 + c + 4], XhB[s * 8 + c + 4]};
        unsigned al[4] = {XlA[s * 8 + c], XlB[s * 8 + c],
                          XlA[s * 8 + c + 4], XlB[s * 8 + c + 4]};
#pragma unroll
        for (int nt = 0; nt < 8; ++nt) {
            const unsigned* wh = Wh + (nt * 8 + r) * XPAD + s * 8;
            const unsigned* wl = Wl + (nt * 8 + r) * XPAD + s * 8;
            unsigned bh[2] = {wh[c], wh[c + 4]};
            unsigned bl[2] = {wl[c], wl[c + 4]};
            mma_bf16(acc[nt], ah, bh);   // x_hi * w_hi
            mma_bf16(acc[nt], al, bh);   // x_lo * w_hi
            mma_bf16(acc[nt], ah, bl);   // x_hi * w_lo
        }
    }
    __syncwarp();   // own-strip rows only; warp-local handoff
    unsigned* XhO = Xh + (w * 16 + r) * XPAD;
    unsigned* XhO8 = XhO + 8 * XPAD;
    unsigned* XlO = Xl + (w * 16 + r) * XPAD;
    unsigned* XlO8 = XlO + 8 * XPAD;
#pragma unroll
    for (int nt = 0; nt < 8; ++nt) {
        int kw = nt * 4 + c;
        float t0 = my_tanh(acc[nt][0]), t1 = my_tanh(acc[nt][1]);
        float t2 = my_tanh(acc[nt][2]), t3 = my_tanh(acc[nt][3]);
        unsigned hw, lw;
        split_word(t0, t1, hw, lw);
        XhO[kw] = hw;
        XlO[kw] = lw;
        split_word(t2, t3, hw, lw);
        XhO8[kw] = hw;
        XlO8[kw] = lw;
    }
    __syncwarp();
}

__global__ __launch_bounds__(256, 3) void pair_kernel(
    const float* __restrict__ ab1, const float* __restrict__ ab2,
    const float* __restrict__ aw3, const float* __restrict__ ab3,
    const float* __restrict__ ab0, const int* __restrict__ dimp) {
    extern __shared__ __align__(16) char smem_raw[];
    PairSmem* sm = (PairSmem*)smem_raw;
    int dim = read_dim(dimp);
    int p0 = blockIdx.x * BLKP;
    if (p0 >= dim) return;               // uniform block exit
    int b = blockIdx.y, t = threadIdx.x;

    // ---- copy preconverted split-bf16 weights (4 contiguous arrays) ----
    {
        uint4* dstv = (uint4*)sm->Wh1;
#pragma unroll
        for (int i = 0; i < 9; ++i) dstv[t + 256 * i] = d_Wpre4[t + 256 * i];
        if (t < 64) {
            sm->b1[t] = ab1[t];
            sm->b2[t] = ab2[t];
            sm->b0[t] = ab0[t];
            sm->Gg[t] = d_Gg[b * 64 + t];
            sm->W3[2 * t + 0] = aw3[2 * t + 0];
            sm->W3[2 * t + 1] = aw3[2 * t + 1];
        }
        if (t < 2) sm->b3[t] = ab3[t];
    }
    // warp 0 computes SA = sum_k |W3[k][0]| via shuffle reduce (from global)
    if (t < 32) {
        float s = fabsf(aw3[2 * t]) + fabsf(aw3[2 * (t + 32)]);
#pragma unroll
        for (int o = 16; o; o >>= 1) s += __shfl_xor_sync(0xffffffffu, s, o);
        if (t == 0) sm->sSA = s;
    }
    __syncthreads();
    float SA = sm->sSA;

    // ---- layer 0: 2 threads per pair, convert-as-you-go (low register load) ----
    {
        int lp = t >> 1, half = t & 1;
        int p = p0 + lp;
        int cnt = d_count[b];
        int kb = half * 32;
        unsigned* xh = sm->Xh + lp * XPAD + half * 16;
        unsigned* xl = sm->Xl + lp * XPAD + half * 16;
        if (p < cnt && p < dim) {
            int q = d_order[b * DIMMAX + p];
            int i1 = q / Nn, i2 = q - i1 * Nn;
            const float4* Ga = (const float4*)(d_A + ((size_t)(b * Nn + i1)) * 64 + kb);
            const float4* Cc = (const float4*)(d_C + ((size_t)(b * Nn + i2)) * 64 + kb);
#pragma unroll
            for (int kk = 0; kk < 8; ++kk) {
                float4 a = Ga[kk], c4 = Cc[kk];
                int k = kb + 4 * kk;
                float v0 = my_tanh(sm->Gg[k + 0] + a.x + c4.x);
                float v1 = my_tanh(sm->Gg[k + 1] + a.y + c4.y);
                float v2 = my_tanh(sm->Gg[k + 2] + a.z + c4.z);
                float v3 = my_tanh(sm->Gg[k + 3] + a.w + c4.w);
                unsigned hw, lw;
                split_word(v0, v1, hw, lw);
                xh[2 * kk] = hw;
                xl[2 * kk] = lw;
                split_word(v2, v3, hw, lw);
                xh[2 * kk + 1] = hw;
                xl[2 * kk + 1] = lw;
            }
        } else {
            // invalid / out-of-range: zeroed input -> pre-activation = b0
#pragma unroll
            for (int kk = 0; kk < 16; ++kk) {
                float v0 = my_tanh(sm->b0[kb + 2 * kk]);
                float v1 = my_tanh(sm->b0[kb + 2 * kk + 1]);
                unsigned hw, lw;
                split_word(v0, v1, hw, lw);
                xh[kk] = hw;
                xl[kk] = lw;
            }
        }
    }
    __syncwarp();

    int w = t >> 5, lane = t & 31;
    mma_layer(sm->Xh, sm->Xl, sm->Wh1, sm->Wl1, sm->b1, w, lane);
    mma_layer(sm->Xh, sm->Xl, sm->Wh2, sm->Wl2, sm->b2, w, lane);

    // ---- layer 3 + block partial softmax sum ----
    float ev = 0.f;
    {
        int lp = t >> 1, half = t & 1;
        int p = p0 + lp;
        const unsigned* xh = sm->Xh + lp * XPAD + half * 16;
        const unsigned* xl = sm->Xl + lp * XPAD + half * 16;
        float lg = 0.f, bq = 0.f;
        int kb = half * 32;
#pragma unroll
        for (int kk2 = 0; kk2 < 16; ++kk2) {
            __nv_bfloat162 hh = *reinterpret_cast<const __nv_bfloat162*>(xh + kk2);
            __nv_bfloat162 ll = *reinterpret_cast<const __nv_bfloat162*>(xl + kk2);
            float h0 = __bfloat162float(hh.x) + __bfloat162float(ll.x);
            float h1 = __bfloat162float(hh.y) + __bfloat162float(ll.y);
            int k = kb + 2 * kk2;
            lg += h0 * sm->W3[2 * k + 0] + h1 * sm->W3[2 * k + 2];
            bq += h0 * sm->W3[2 * k + 1] + h1 * sm->W3[2 * k + 3];
        }
        lg += __shfl_xor_sync(0xffffffffu, lg, 1);
        bq += __shfl_xor_sync(0xffffffffu, bq, 1);
        if (half == 0 && p < dim) {
            // e = exp(logit - (b3 + SA)); softmax is shift-invariant
            float e = __expf(lg - SA);
            d_logit[b * DIMMAX + p] = e;
            d_sig[b * DIMMAX + p] = 1.0f / (1.0f + __expf(-(bq + sm->b3[1])));
            ev = e;
        }
    }
    // block-level sum of e -> atomic into d_esum[b]
#pragma unroll
    for (int o = 16; o; o >>= 1) ev += __shfl_xor_sync(0xffffffffu, ev, o);
    if (lane == 0) sm->epart[w] = ev;
    __syncthreads();
    if (t == 0) {
        float s2 = 0.f;
#pragma unroll
        for (int i = 0; i < 8; ++i) s2 += sm->epart[i];
        atomicAdd(&d_esum[b], s2);
    }
}

// ---------------- kernel 3: wide normalize + scatter ----------------
__global__ void scatter_kernel(float* __restrict__ out, const int* __restrict__ dimp) {
    int dim = read_dim(dimp);
    int b = blockIdx.y;
    int p = blockIdx.x * 256 + threadIdx.x;
    if (p >= dim) return;
    if (p >= d_count[b]) return;  // valid == 0 -> contributes zeros only
    float inv = 1.0f / d_esum[b];
    int q = d_order[b * DIMMAX + p];
    float pi = d_logit[b * DIMMAX + p] * inv;
    float sg = d_sig[b * DIMMAX + p];
    float* ob = out + (size_t)b * 20000;
    ob[q] = pi * sg;
    ob[10000 + q] = pi * (1.0f - sg);
}

// ---------------- launcher (3 launches, single stream) ----------------
extern "C" void kernel_launch(void* const* d_in, const int* in_sizes, int n_in,
                              void* d_out, int out_size) {
    const float* emb = (const float*)d_in[0];
    const int* dimp;
    int base;
    if (n_in >= 18 && in_sizes[1] == 1) {   // dict order: emb, dim, actor..., critic...
        dimp = (const int*)d_in[1];
        base = 2;
    } else {                                // signature order: emb, actor..., critic..., dim
        dimp = (const int*)d_in[n_in - 1];
        base = 1;
    }
    const float* aw0 = (const float*)d_in[base + 0];
    const float* ab0 = (const float*)d_in[base + 1];
    const float* aw1 = (const float*)d_in[base + 2];
    const float* ab1 = (const float*)d_in[base + 3];
    const float* aw2 = (const float*)d_in[base + 4];
    const float* ab2 = (const float*)d_in[base + 5];
    const float* aw3 = (const float*)d_in[base + 6];
    const float* ab3 = (const float*)d_in[base + 7];
    const float* cw0 = (const float*)d_in[base + 8];
    const float* cb0 = (const float*)d_in[base + 9];
    const float* cw1 = (const float*)d_in[base + 10];
    const float* cb1 = (const float*)d_in[base + 11];
    const float* cw2 = (const float*)d_in[base + 12];
    const float* cb2 = (const float*)d_in[base + 13];
    const float* cw3 = (const float*)d_in[base + 14];
    const float* cb3 = (const float*)d_in[base + 15];

    float* out = (float*)d_out;
    int voff = out_size - Bz;  // value slot after the filled region (expect 640000)

    static int init_done = 0;
    if (!init_done) {
        cudaFuncSetAttribute(pair_kernel, cudaFuncAttributeMaxDynamicSharedMemorySize,
                             PAIR_SMEM_BYTES);
        cudaFuncSetAttribute(prep_kernel, cudaFuncAttributeMaxDynamicSharedMemorySize,
                             PREP_SMEM);
        init_done = 1;
    }

    prep_kernel<<<146, 256, PREP_SMEM>>>(emb, aw0, ab0, aw1, aw2,
                                         cw0, cb0, cw1, cb1, cw2, cb2,
                                         cw3, cb3, out, voff, dimp);
    pair_kernel<<<dim3(PBLK, Bz), 256, PAIR_SMEM_BYTES>>>(ab1, ab2, aw3, ab3,
                                                          ab0, dimp);
    scatter_kernel<<<dim3(40, Bz), 256>>>(out, dimp);
}

// round 17
// speedup vs baseline: 1.1760x; 1.0382x over previous
#include <cuda_runtime.h>
#include <cuda_bf16.h>
#include <cstdint>
#include <math.h>

#define Bz     32
#define Nn     100
#define Ff     514
#define FE     614      // 514 feats + 100 mask cols
#define ROWSE  101
#define NN2    10000
#define DIMMAX 10000
#define BLKP   128      // pairs per tile in pair kernel
#define PBLK   79       // max tiles per batch
#define PERS   444      // persistent grid: 148 SM x 3 blocks
#define XPAD   36
#define ASTR   20       // word stride in ac GEMM smem (20 ≡ 4 mod 32 -> conflict-free)

// ---------------- scratch (static device globals; no allocation) ----------------
__device__ int   d_order[Bz * DIMMAX];
__device__ int   d_count[Bz];
__device__ float d_Gg[Bz * 64];
__device__ float d_A[Bz * Nn * 64];
__device__ float d_C[Bz * Nn * 64];
__device__ float d_logit[Bz * DIMMAX];   // holds e = exp(logit - shift)
__device__ float d_sig[Bz * DIMMAX];
__device__ float d_esum[Bz];
__device__ uint4 d_Wpre4[2304];          // pair weights, split-bf16 padded layout

// ---------------- small helpers ----------------
__device__ __forceinline__ int read_dim(const int* p) {
    int v = *p;
    if (v < 1 || v > DIMMAX) {            // safety: tolerate float-encoded scalar
        float f = __int_as_float(v);
        v = (int)f;
    }
    if (v < 0) v = 0;
    if (v > DIMMAX) v = DIMMAX;
    return v;
}

// Eigen-style rational minimax tanh: 1 MUFU (rcp) instead of 2 (ex2+rcp).
__device__ __forceinline__ float my_tanh(float x) {
    x = fminf(fmaxf(x, -7.90531110763549805f), 7.90531110763549805f);
    float x2 = x * x;
    float p = fmaf(x2, -2.76076847742355e-16f, 2.00018790482477e-13f);
    p = fmaf(x2, p, -8.60467152213735e-11f);
    p = fmaf(x2, p, 5.12229709037114e-08f);
    p = fmaf(x2, p, 1.48572235717979e-05f);
    p = fmaf(x2, p, 6.37261928875436e-04f);
    p = fmaf(x2, p, 4.89352455891786e-03f);
    p = x * p;
    float q = fmaf(x2, 1.19825839466702e-06f, 1.18534705686654e-04f);
    q = fmaf(x2, q, 2.26843463243900e-03f);
    q = fmaf(x2, q, 4.89352518554385e-03f);
    return __fdividef(p, q);
}

__device__ __forceinline__ unsigned pack_bf(__nv_bfloat16 a, __nv_bfloat16 b) {
    __nv_bfloat162 v;
    v.x = a;  // low half
    v.y = b;  // high half
    return *reinterpret_cast<unsigned*>(&v);
}

__device__ __forceinline__ void split_word(float a, float b, unsigned& hw, unsigned& lw) {
    __nv_bfloat16 ha = __float2bfloat16(a), hb = __float2bfloat16(b);
    hw = pack_bf(ha, hb);
    lw = pack_bf(__float2bfloat16(a - __bfloat162float(ha)),
                 __float2bfloat16(b - __bfloat162float(hb)));
}

__device__ __forceinline__ void mma_bf16(float (&d)[4], const unsigned (&a)[4],
                                         const unsigned (&b)[2]) {
    asm volatile(
        "mma.sync.aligned.m16n8k16.row.col.f32.bf16.bf16.f32 "
        "{%0,%1,%2,%3}, {%4,%5,%6,%7}, {%8,%9}, {%0,%1,%2,%3};"
        : "+f"(d[0]), "+f"(d[1]), "+f"(d[2]), "+f"(d[3])
        : "r"(a[0]), "r"(a[1]), "r"(a[2]), "r"(a[3]), "r"(b[0]), "r"(b[1]));
}

// ================= prep kernel: flat 146 blocks: ac(50)/scan(32)/head(32)/zero(32)
// ac dynamic smem: 2 buffers x (128 W + 64 A rows) x 20 words x 2 (hi,lo) = 61440B
#define PREP_SMEM (2 * (128 + 64) * 2 * ASTR * 4)

__device__ void scan_role(const float* __restrict__ emb, int b, int dim, char* sh) {
    int t = threadIdx.x;           // 256
    int lane = t & 31, w = t >> 5; // 8 warps
    unsigned* bal = (unsigned*)sh;         // [320]
    int* pre = (int*)(sh + 320 * 4);       // [320]
    // phase 1: batched loads (20 in flight), then ballots
#pragma unroll
    for (int hf = 0; hf < 2; ++hf) {
        float v[20];
#pragma unroll
        for (int c2 = 0; c2 < 20; ++c2) {
            int c = hf * 20 + c2;
            int idx = c * 256 + t;
            float val = 0.f;
            if (idx < NN2) {
                int i = idx / Nn, j = idx - i * Nn;
                val = emb[(size_t)(b * ROWSE + 1 + i) * FE + Ff + j];
            }
            v[c2] = val;
        }
#pragma unroll
        for (int c2 = 0; c2 < 20; ++c2) {
            unsigned bl = __ballot_sync(0xffffffffu, v[c2] > 0.5f);
            if (lane == 0) bal[(hf * 20 + c2) * 8 + w] = bl;
        }
    }
    __syncthreads();
    if (t < 32) {
        int loc[10];
        int s = 0;
#pragma unroll
        for (int k = 0; k < 10; ++k) {
            int v = __popc(bal[lane * 10 + k]);
            loc[k] = s;
            s += v;
        }
        int p = s;
#pragma unroll
        for (int o = 1; o < 32; o <<= 1) {
            int n = __shfl_up_sync(0xffffffffu, p, o);
            if (lane >= o) p += n;
        }
        int off = p - s;
#pragma unroll
        for (int k = 0; k < 10; ++k) pre[lane * 10 + k] = off + loc[k];
        if (lane == 31) d_count[b] = p;
    }
    __syncthreads();
#pragma unroll
    for (int c = 0; c < 40; ++c) {
        unsigned bl = bal[c * 8 + w];
        if ((bl >> lane) & 1u) {
            int rank = pre[c * 8 + w] + __popc(bl & ((1u << lane) - 1u));
            if (rank < dim) d_order[b * DIMMAX + rank] = c * 256 + t;
        }
    }
}

__device__ void head_role(const float* __restrict__ emb,
                          const float* __restrict__ aw0, const float* __restrict__ ab0,
                          const float* __restrict__ cw0, const float* __restrict__ cb0,
                          const float* __restrict__ cw1, const float* __restrict__ cb1,
                          const float* __restrict__ cw2, const float* __restrict__ cb2,
                          const float* __restrict__ cw3, const float* __restrict__ cb3,
                          float* __restrict__ out, int voff, int b, char* sh) {
    float* row = (float*)sh;              // [516]
    float* part = row + 516;              // [256]
    float* ha = part + 256;               // [64]
    float* hb = ha + 64;                  // [64]
    int t = threadIdx.x;                  // 256
    for (int k = t; k < Ff; k += 256) row[k] = emb[(size_t)b * ROWSE * FE + k];
    __syncthreads();
    int j = t & 63, ks = t >> 6;  // 4-way k split
    {
        float acc = 0.f;
        for (int k = ks; k < Ff; k += 4) acc += row[k] * aw0[(size_t)k * 64 + j];
        part[t] = acc;
    }
    __syncthreads();
    if (t < 64) {
        float s = ab0[j] + part[j] + part[64 + j] + part[128 + j] + part[192 + j];
        d_Gg[b * 64 + j] = s;
    }
    __syncthreads();
    {
        float acc = 0.f;
        for (int k = ks; k < Ff; k += 4) acc += row[k] * cw0[(size_t)k * 64 + j];
        part[t] = acc;
    }
    __syncthreads();
    if (t < 64) {
        float s = cb0[j] + part[j] + part[64 + j] + part[128 + j] + part[192 + j];
        ha[j] = my_tanh(s);
    }
    __syncthreads();
    if (t < 64) {
        float acc = cb1[t];
        for (int k = 0; k < 64; ++k) acc += ha[k] * cw1[k * 64 + t];
        hb[t] = my_tanh(acc);
    }
    __syncthreads();
    if (t < 64) {
        float acc = cb2[t];
        for (int k = 0; k < 64; ++k) acc += hb[k] * cw2[k * 64 + t];
        ha[t] = my_tanh(acc);
    }
    __syncthreads();
    if (t == 0) {
        float v = cb3[0];
        for (int k = 0; k < 64; ++k) v += ha[k] * cw3[k];
        out[voff + b] = v;
    }
}

// [A|C] = nodes[3200,514] @ [W0_A | W0_C], bf16 3-term split tensor-core GEMM.
// 64-row x 128-col tiles (50 blocks), K padded 514 -> 544 (17 x k32 chunks).
__device__ void ac_mma_role(const float* __restrict__ emb,
                            const float* __restrict__ w0, int blk, char* sh) {
    int t = threadIdx.x;   // 256
    unsigned* buf = (unsigned*)sh;
    const int BUFW = (128 + 64) * 2 * ASTR;        // 7680 words per buffer
    const float* wA = w0 + (size_t)Ff * 64;        // A weights [514][64]
    const float* wC = wA + (size_t)Ff * 64;        // C weights [514][64]
    int m0 = blk * 64;

    // A staging: row = t>>2 (0..63), q = t&3 (4 threads/row, 4 words each)
    int arow = t >> 2, q = t & 3;
    int gr = m0 + arow;
    int bb = gr / Nn, node = gr - bb * Nn;
    const float* asrc = emb + (size_t)(bb * ROWSE + 1 + node) * FE;

    float wreg[16];
    float areg[8];

#define ACL(kb)                                                              \
    do {                                                                     \
        _Pragma("unroll") for (int i = 0; i < 8; ++i) {                      \
            int e = t + 256 * i;                                             \
            int n = e & 127, wd = e >> 7;                                    \
            int k0 = (kb) + 2 * wd;                                          \
            const float* src = (n < 64) ? (wA + n) : (wC + (n - 64));        \
            wreg[2 * i] = (k0 < Ff) ? src[(size_t)k0 * 64] : 0.f;            \
            wreg[2 * i + 1] = (k0 + 1 < Ff) ? src[(size_t)(k0 + 1) * 64] : 0.f; \
        }                                                                    \
        _Pragma("unroll") for (int jj = 0; jj < 4; ++jj) {                   \
            int ka = (kb) + 8 * q + 2 * jj;                                  \
            float2 v2 = make_float2(0.f, 0.f);                               \
            if (ka < Ff) {                                                   \
                v2 = *(const float2*)(asrc + ka);                            \
                if (ka + 1 >= Ff) v2.y = 0.f;                                \
            }                                                                \
            areg[2 * jj] = v2.x;                                             \
            areg[2 * jj + 1] = v2.y;                                         \
        }                                                                    \
    } while (0)

#define ACS(dst)                                                             \
    do {                                                                     \
        unsigned* Wh_ = (dst);                                               \
        unsigned* Wl_ = Wh_ + 128 * ASTR;                                    \
        unsigned* Ah_ = Wl_ + 128 * ASTR;                                    \
        unsigned* Al_ = Ah_ + 64 * ASTR;                                     \
        _Pragma("unroll") for (int i = 0; i < 8; ++i) {                      \
            int e = t + 256 * i;                                             \
            int n = e & 127, wd = e >> 7;                                    \
            unsigned hw, lw;                                                 \
            split_word(wreg[2 * i], wreg[2 * i + 1], hw, lw);                \
            Wh_[n * ASTR + wd] = hw;                                         \
            Wl_[n * ASTR + wd] = lw;                                         \
        }                                                                    \
        _Pragma("unroll") for (int jj = 0; jj < 4; ++jj) {                   \
            unsigned hw, lw;                                                 \
            split_word(areg[2 * jj], areg[2 * jj + 1], hw, lw);              \
            Ah_[arow * ASTR + q * 4 + jj] = hw;                              \
            Al_[arow * ASTR + q * 4 + jj] = lw;                              \
        }                                                                    \
    } while (0)

    ACL(0);
    ACS(buf);
    ACL(32);   // regs now hold chunk 1
    __syncthreads();

    int w = t >> 5, lane = t & 31;
    int r = lane >> 2, c = lane & 3;
    int ms = (w & 3) * 16;       // m-strip base within 64-row tile
    int ng = (w >> 2) * 64;      // n-group base (8 n8 tiles)

    float acc[8][4];
#pragma unroll
    for (int nt = 0; nt < 8; ++nt)
#pragma unroll
        for (int i2 = 0; i2 < 4; ++i2) acc[nt][i2] = 0.f;

    for (int kc = 0; kc < 17; ++kc) {
        unsigned* cur = buf + (kc & 1) * BUFW;
        unsigned* alt = buf + ((kc & 1) ^ 1) * BUFW;
        const unsigned* Wh = cur;
        const unsigned* Wl = Wh + 128 * ASTR;
        const unsigned* Ah = Wl + 128 * ASTR;
        const unsigned* Al = Ah + 64 * ASTR;
#pragma unroll
        for (int s2 = 0; s2 < 2; ++s2) {
            int kwb = s2 * 8;
            const unsigned* aha = Ah + (ms + r) * ASTR + kwb;
            const unsigned* ala = Al + (ms + r) * ASTR + kwb;
            unsigned ah[4] = {aha[c], aha[8 * ASTR + c], aha[c + 4], aha[8 * ASTR + c + 4]};
            unsigned al[4] = {ala[c], ala[8 * ASTR + c], ala[c + 4], ala[8 * ASTR + c + 4]};
#pragma unroll
            for (int nt = 0; nt < 8; ++nt) {
                const unsigned* wh = Wh + (ng + nt * 8 + r) * ASTR + kwb;
                const unsigned* wl = Wl + (ng + nt * 8 + r) * ASTR + kwb;
                unsigned bh[2] = {wh[c], wh[c + 4]};
                unsigned bl[2] = {wl[c], wl[c + 4]};
                mma_bf16(acc[nt], ah, bh);   // a_hi * w_hi
                mma_bf16(acc[nt], al, bh);   // a_lo * w_hi
                mma_bf16(acc[nt], ah, bl);   // a_hi * w_lo
            }
        }
        if (kc < 16) {
            ACS(alt);                            // store chunk kc+1
            if (kc < 15) ACL((kc + 2) * 32);     // load chunk kc+2
        }
        __syncthreads();
    }
#undef ACL
#undef ACS

    // epilogue: fp32 results -> d_A / d_C
#pragma unroll
    for (int nt = 0; nt < 8; ++nt) {
        int j = ng + nt * 8 + 2 * c;
        int gr0 = m0 + ms + r, gr1 = gr0 + 8;
        float* dst = (j < 64) ? d_A : d_C;
        int jj = (j < 64) ? j : j - 64;
        *(float2*)(dst + (size_t)gr0 * 64 + jj) = make_float2(acc[nt][0], acc[nt][1]);
        *(float2*)(dst + (size_t)gr1 * 64 + jj) = make_float2(acc[nt][2], acc[nt][3]);
    }
}

// zero output slab + esum, and convert this block's slice of pair weights
__device__ void zero_role(float* __restrict__ out, int b,
                          const float* __restrict__ aw1,
                          const float* __restrict__ aw2) {
    float4 z = make_float4(0.f, 0.f, 0.f, 0.f);
    float4* ob = (float4*)(out + (size_t)b * 20000);
    int t = threadIdx.x;
    for (int i = t; i < 5000; i += 256) ob[i] = z;
    if (t == 0) d_esum[b] = 0.f;
    // convert slice: elements e in [b*128, b*128+128) of aw1 and aw2
    if (t < 128) {
        __nv_bfloat16* wp = (__nv_bfloat16*)d_Wpre4;
        int e = b * 128 + t;
        int k = e >> 6, n = e & 63;
        int ei = n * 72 + k;
        float w1v = aw1[e], w2v = aw2[e];
        __nv_bfloat16 h1 = __float2bfloat16(w1v);
        wp[0 * 4608 + ei] = h1;
        wp[1 * 4608 + ei] = __float2bfloat16(w1v - __bfloat162float(h1));
        __nv_bfloat16 h2 = __float2bfloat16(w2v);
        wp[2 * 4608 + ei] = h2;
        wp[3 * 4608 + ei] = __float2bfloat16(w2v - __bfloat162float(h2));
    }
}

__global__ void prep_kernel(const float* __restrict__ emb,
                            const float* __restrict__ aw0, const float* __restrict__ ab0,
                            const float* __restrict__ aw1, const float* __restrict__ aw2,
                            const float* __restrict__ cw0, const float* __restrict__ cb0,
                            const float* __restrict__ cw1, const float* __restrict__ cb1,
                            const float* __restrict__ cw2, const float* __restrict__ cb2,
                            const float* __restrict__ cw3, const float* __restrict__ cb3,
                            float* __restrict__ out, int voff,
                            const int* __restrict__ dimp) {
    extern __shared__ __align__(16) char sh[];
    int bid = blockIdx.x;
    if (bid < 50) {
        ac_mma_role(emb, aw0, bid, sh);
    } else if (bid < 82) {
        scan_role(emb, bid - 50, read_dim(dimp), sh);
    } else if (bid < 114) {
        head_role(emb, aw0, ab0, cw0, cb0, cw1, cb1, cw2, cb2, cw3, cb3,
                  out, voff, bid - 82, sh);
    } else {
        zero_role(out, bid - 114, aw1, aw2);
    }
}

// ============== pair kernel v10: persistent grid-stride, bf16 MMA ===============
// Weights staged ONCE per block; loop over (batch, tile) work items.
// 128 pairs/tile, 8 warps; warp owns a 16-row m-strip through both layers.
// X, W stored as bf16x2 words (hi + lo arrays), XPAD=36 => conflict-free frags.
struct PairSmem {
    unsigned Wh1[64 * XPAD], Wl1[64 * XPAD];
    unsigned Wh2[64 * XPAD], Wl2[64 * XPAD];
    unsigned Xh[128 * XPAD], Xl[128 * XPAD];
    float W3[128];                // [k][2]
    float b1[64], b2[64], b0[64], Gg[64];
    float b3[2];
    float epart[8];
    float sSA;
};
#define PAIR_SMEM_BYTES ((int)sizeof(PairSmem))

__device__ __forceinline__ void mma_layer(unsigned* __restrict__ Xh,
                                          unsigned* __restrict__ Xl,
                                          const unsigned* __restrict__ Wh,
                                          const unsigned* __restrict__ Wl,
                                          const float* __restrict__ bias,
                                          int w, int lane) {
    int r = lane >> 2, c = lane & 3;
    float acc[8][4];
#pragma unroll
    for (int nt = 0; nt < 8; ++nt) {
        float bv0 = bias[nt * 8 + 2 * c], bv1 = bias[nt * 8 + 2 * c + 1];
        acc[nt][0] = bv0; acc[nt][1] = bv1; acc[nt][2] = bv0; acc[nt][3] = bv1;
    }
    const unsigned* XhA = Xh + (w * 16 + r) * XPAD;
    const unsigned* XhB = XhA + 8 * XPAD;
    const unsigned* XlA = Xl + (w * 16 + r) * XPAD;
    const unsigned* XlB = XlA + 8 * XPAD;
#pragma unroll
    for (int s = 0; s < 4; ++s) {
        unsigned ah[4] = {XhA[s * 8 + c], XhB[s * 8 + c],
                          XhA[s * 8 + c + 4], XhB[s * 8 + c + 4]};
        unsigned al[4] = {XlA[s * 8 + c], XlB[s * 8 + c],
                          XlA[s * 8 + c + 4], XlB[s * 8 + c + 4]};
#pragma unroll
        for (int nt = 0; nt < 8; ++nt) {
            const unsigned* wh = Wh + (nt * 8 + r) * XPAD + s * 8;
            const unsigned* wl = Wl + (nt * 8 + r) * XPAD + s * 8;
            unsigned bh[2] = {wh[c], wh[c + 4]};
            unsigned bl[2] = {wl[c], wl[c + 4]};
            mma_bf16(acc[nt], ah, bh);   // x_hi * w_hi
            mma_bf16(acc[nt], al, bh);   // x_lo * w_hi
            mma_bf16(acc[nt], ah, bl);   // x_hi * w_lo
        }
    }
    __syncwarp();   // own-strip rows only; warp-local handoff
    unsigned* XhO = Xh + (w * 16 + r) * XPAD;
    unsigned* XhO8 = XhO + 8 * XPAD;
    unsigned* XlO = Xl + (w * 16 + r) * XPAD;
    unsigned* XlO8 = XlO + 8 * XPAD;
#pragma unroll
    for (int nt = 0; nt < 8; ++nt) {
        int kw = nt * 4 + c;
        float t0 = my_tanh(acc[nt][0]), t1 = my_tanh(acc[nt][1]);
        float t2 = my_tanh(acc[nt][2]), t3 = my_tanh(acc[nt][3]);
        unsigned hw, lw;
        split_word(t0, t1, hw, lw);
        XhO[kw] = hw;
        XlO[kw] = lw;
        split_word(t2, t3, hw, lw);
        XhO8[kw] = hw;
        XlO8[kw] = lw;
    }
    __syncwarp();
}

__global__ __launch_bounds__(256, 3) void pair_kernel(
    const float* __restrict__ ab1, const float* __restrict__ ab2,
    const float* __restrict__ aw3, const float* __restrict__ ab3,
    const float* __restrict__ ab0, const int* __restrict__ dimp) {
    extern __shared__ __align__(16) char smem_raw[];
    PairSmem* sm = (PairSmem*)smem_raw;
    int dim = read_dim(dimp);
    int t = threadIdx.x;
    int w = t >> 5, lane = t & 31;

    // ---- stage weights/biases ONCE per block ----
    {
        uint4* dstv = (uint4*)sm->Wh1;
#pragma unroll
        for (int i = 0; i < 9; ++i) dstv[t + 256 * i] = d_Wpre4[t + 256 * i];
        if (t < 64) {
            sm->b1[t] = ab1[t];
            sm->b2[t] = ab2[t];
            sm->b0[t] = ab0[t];
            sm->W3[2 * t + 0] = aw3[2 * t + 0];
            sm->W3[2 * t + 1] = aw3[2 * t + 1];
        }
        if (t < 2) sm->b3[t] = ab3[t];
    }
    // warp 0 computes SA = sum_k |W3[k][0]| via shuffle reduce (from global)
    if (t < 32) {
        float s = fabsf(aw3[2 * t]) + fabsf(aw3[2 * (t + 32)]);
#pragma unroll
        for (int o = 16; o; o >>= 1) s += __shfl_xor_sync(0xffffffffu, s, o);
        if (t == 0) sm->sSA = s;
    }
    __syncthreads();
    float SA = sm->sSA;

    int nblk = (dim + BLKP - 1) / BLKP;
    if (nblk > PBLK) nblk = PBLK;
    int ntile = nblk * Bz;

    for (int tile = blockIdx.x; tile < ntile; tile += gridDim.x) {
        int b = tile / nblk;
        int p0 = (tile - b * nblk) * BLKP;

        // guard: previous tile's readers done before overwriting Gg / X
        __syncthreads();
        if (t < 64) sm->Gg[t] = d_Gg[b * 64 + t];
        __syncthreads();

        // ---- layer 0: 2 threads per pair, convert-as-you-go ----
        {
            int lp = t >> 1, half = t & 1;
            int p = p0 + lp;
            int cnt = d_count[b];
            int kb = half * 32;
            unsigned* xh = sm->Xh + lp * XPAD + half * 16;
            unsigned* xl = sm->Xl + lp * XPAD + half * 16;
            if (p < cnt && p < dim) {
                int q = d_order[b * DIMMAX + p];
                int i1 = q / Nn, i2 = q - i1 * Nn;
                const float4* Ga = (const float4*)(d_A + ((size_t)(b * Nn + i1)) * 64 + kb);
                const float4* Cc = (const float4*)(d_C + ((size_t)(b * Nn + i2)) * 64 + kb);
#pragma unroll
                for (int kk = 0; kk < 8; ++kk) {
                    float4 a = Ga[kk], c4 = Cc[kk];
                    int k = kb + 4 * kk;
                    float v0 = my_tanh(sm->Gg[k + 0] + a.x + c4.x);
                    float v1 = my_tanh(sm->Gg[k + 1] + a.y + c4.y);
                    float v2 = my_tanh(sm->Gg[k + 2] + a.z + c4.z);
                    float v3 = my_tanh(sm->Gg[k + 3] + a.w + c4.w);
                    unsigned hw, lw;
                    split_word(v0, v1, hw, lw);
                    xh[2 * kk] = hw;
                    xl[2 * kk] = lw;
                    split_word(v2, v3, hw, lw);
                    xh[2 * kk + 1] = hw;
                    xl[2 * kk + 1] = lw;
                }
            } else {
                // invalid / out-of-range: zeroed input -> pre-activation = b0
#pragma unroll
                for (int kk = 0; kk < 16; ++kk) {
                    float v0 = my_tanh(sm->b0[kb + 2 * kk]);
                    float v1 = my_tanh(sm->b0[kb + 2 * kk + 1]);
                    unsigned hw, lw;
                    split_word(v0, v1, hw, lw);
                    xh[kk] = hw;
                    xl[kk] = lw;
                }
            }
        }
        __syncwarp();

        mma_layer(sm->Xh, sm->Xl, sm->Wh1, sm->Wl1, sm->b1, w, lane);
        mma_layer(sm->Xh, sm->Xl, sm->Wh2, sm->Wl2, sm->b2, w, lane);

        // ---- layer 3 + tile partial softmax sum ----
        float ev = 0.f;
        {
            int lp = t >> 1, half = t & 1;
            int p = p0 + lp;
            const unsigned* xh = sm->Xh + lp * XPAD + half * 16;
            const unsigned* xl = sm->Xl + lp * XPAD + half * 16;
            float lg = 0.f, bq = 0.f;
            int kb = half * 32;
#pragma unroll
            for (int kk2 = 0; kk2 < 16; ++kk2) {
                __nv_bfloat162 hh = *reinterpret_cast<const __nv_bfloat162*>(xh + kk2);
                __nv_bfloat162 ll = *reinterpret_cast<const __nv_bfloat162*>(xl + kk2);
                float h0 = __bfloat162float(hh.x) + __bfloat162float(ll.x);
                float h1 = __bfloat162float(hh.y) + __bfloat162float(ll.y);
                int k = kb + 2 * kk2;
                lg += h0 * sm->W3[2 * k + 0] + h1 * sm->W3[2 * k + 2];
                bq += h0 * sm->W3[2 * k + 1] + h1 * sm->W3[2 * k + 3];
            }
            lg += __shfl_xor_sync(0xffffffffu, lg, 1);
            bq += __shfl_xor_sync(0xffffffffu, bq, 1);
            if (half == 0 && p < dim) {
                // e = exp(logit - (b3 + SA)); softmax is shift-invariant
                float e = __expf(lg - SA);
                d_logit[b * DIMMAX + p] = e;
                d_sig[b * DIMMAX + p] = 1.0f / (1.0f + __expf(-(bq + sm->b3[1])));
                ev = e;
            }
        }
        // tile-level sum of e -> atomic into d_esum[b]
#pragma unroll
        for (int o = 16; o; o >>= 1) ev += __shfl_xor_sync(0xffffffffu, ev, o);
        if (lane == 0) sm->epart[w] = ev;
        __syncthreads();
        if (t == 0) {
            float s2 = 0.f;
#pragma unroll
            for (int i = 0; i < 8; ++i) s2 += sm->epart[i];
            atomicAdd(&d_esum[b], s2);
        }
    }
}

// ---------------- kernel 3: wide normalize + scatter ----------------
__global__ void scatter_kernel(float* __restrict__ out, const int* __restrict__ dimp) {
    int dim = read_dim(dimp);
    int b = blockIdx.y;
    int p = blockIdx.x * 256 + threadIdx.x;
    if (p >= dim) return;
    if (p >= d_count[b]) return;  // valid == 0 -> contributes zeros only
    float inv = 1.0f / d_esum[b];
    int q = d_order[b * DIMMAX + p];
    float pi = d_logit[b * DIMMAX + p] * inv;
    float sg = d_sig[b * DIMMAX + p];
    float* ob = out + (size_t)b * 20000;
    ob[q] = pi * sg;
    ob[10000 + q] = pi * (1.0f - sg);
}

// ---------------- launcher (3 launches, single stream) ----------------
extern "C" void kernel_launch(void* const* d_in, const int* in_sizes, int n_in,
                              void* d_out, int out_size) {
    const float* emb = (const float*)d_in[0];
    const int* dimp;
    int base;
    if (n_in >= 18 && in_sizes[1] == 1) {   // dict order: emb, dim, actor..., critic...
        dimp = (const int*)d_in[1];
        base = 2;
    } else {                                // signature order: emb, actor..., critic..., dim
        dimp = (const int*)d_in[n_in - 1];
        base = 1;
    }
    const float* aw0 = (const float*)d_in[base + 0];
    const float* ab0 = (const float*)d_in[base + 1];
    const float* aw1 = (const float*)d_in[base + 2];
    const float* ab1 = (const float*)d_in[base + 3];
    const float* aw2 = (const float*)d_in[base + 4];
    const float* ab2 = (const float*)d_in[base + 5];
    const float* aw3 = (const float*)d_in[base + 6];
    const float* ab3 = (const float*)d_in[base + 7];
    const float* cw0 = (const float*)d_in[base + 8];
    const float* cb0 = (const float*)d_in[base + 9];
    const float* cw1 = (const float*)d_in[base + 10];
    const float* cb1 = (const float*)d_in[base + 11];
    const float* cw2 = (const float*)d_in[base + 12];
    const float* cb2 = (const float*)d_in[base + 13];
    const float* cw3 = (const float*)d_in[base + 14];
    const float* cb3 = (const float*)d_in[base + 15];

    float* out = (float*)d_out;
    int voff = out_size - Bz;  // value slot after the filled region (expect 640000)

    static int init_done = 0;
    if (!init_done) {
        cudaFuncSetAttribute(pair_kernel, cudaFuncAttributeMaxDynamicSharedMemorySize,
                             PAIR_SMEM_BYTES);
        cudaFuncSetAttribute(prep_kernel, cudaFuncAttributeMaxDynamicSharedMemorySize,
                             PREP_SMEM);
        init_done = 1;
    }

    prep_kernel<<<146, 256, PREP_SMEM>>>(emb, aw0, ab0, aw1, aw2,
                                         cw0, cb0, cw1, cb1, cw2, cb2,
                                         cw3, cb3, out, voff, dimp);
    pair_kernel<<<PERS, 256, PAIR_SMEM_BYTES>>>(ab1, ab2, aw3, ab3, ab0, dimp);
    scatter_kernel<<<dim3(40, Bz), 256>>>(out, dimp);
}